// round 3
// baseline (speedup 1.0000x reference)
#include <cuda_runtime.h>
#include <cstdint>
#include <cstddef>
#include <cmath>

#define DINLINE __device__ __forceinline__

static constexpr int B = 64, H = 1024, E = 1024, S = 2048, VOCAB = 50257;

// ---------------- scratch (__device__ globals: allocation-free) ----------------
__device__ float g_A[B * 2048];          // [x || h0]  [64, 2048]
__device__ float g_gates[2 * B * 4096];  // split-K=2 partials of gates
__device__ float g_h[B * H];             // LSTM output h
__device__ float g_e[B * S];             // raw attention energies
__device__ float g_pm[B * 8];            // per-chunk running max
__device__ float g_pl[B * 8];            // per-chunk running sum
__device__ float g_pctx[B * 8 * H];      // per-chunk unnormalized context
__device__ float g_A2[B * 2048];         // [h || context]
__device__ float g_cop[8 * B * H];       // split-K=8 partials of concat GEMM
__device__ float g_co[B * H];            // tanh(concat)

// ---------------- packed f32x2 helpers (with scalar fallback) ----------------
struct F2 { float x, y; };
DINLINE F2 mkf2(float a, float b) { F2 r; r.x = a; r.y = b; return r; }

#if defined(__CUDA_ARCH__) && (__CUDA_ARCH__ >= 1000)
DINLINE void fma2(F2& d, F2 a, F2 b) {
    unsigned long long dd, aa, bb;
    asm("mov.b64 %0, {%1,%2};" : "=l"(aa) : "f"(a.x), "f"(a.y));
    asm("mov.b64 %0, {%1,%2};" : "=l"(bb) : "f"(b.x), "f"(b.y));
    asm("mov.b64 %0, {%1,%2};" : "=l"(dd) : "f"(d.x), "f"(d.y));
    asm("fma.rn.f32x2 %0, %1, %2, %0;" : "+l"(dd) : "l"(aa), "l"(bb));
    asm("mov.b64 {%0,%1}, %2;" : "=f"(d.x), "=f"(d.y) : "l"(dd));
}
#else
DINLINE void fma2(F2& d, F2 a, F2 b) {
    d.x = fmaf(a.x, b.x, d.x);
    d.y = fmaf(a.y, b.y, d.y);
}
#endif

// ---------------- 1) build A = [emb[seq] || h0] ----------------
__global__ void prep_kernel(const int* __restrict__ seq,
                            const float* __restrict__ embW,
                            const float* __restrict__ h0) {
    int b = blockIdx.x, t = threadIdx.x;
    const float4* er = (const float4*)(embW + (size_t)seq[b] * E);
    const float4* hr = (const float4*)(h0 + (size_t)b * H);
    float4* dst = (float4*)(g_A + (size_t)b * 2048);
    dst[t] = er[t];        // 256 float4 = 1024 floats
    dst[256 + t] = hr[t];
}

// ---------------- generic M=64 GEMM: C = A[64,K] @ W[N,K]^T (+bias) ----------------
// aSel: 0 -> g_A, 1 -> g_A2, 2 -> g_co.  cSel: 0 -> g_gates, 1 -> g_cop, 2 -> Cout.
// W element (n,k) comes from W0 if k<Ks else W1 (fused W_ih|W_hh gates GEMM).
// gridDim.z = split-K factor; partial z writes C + z*64*N. Bias added at z==0 only.
__global__ __launch_bounds__(256) void gemm_kernel(
    int aSel, int K, int Ks,
    const float* __restrict__ W0, const float* __restrict__ W1,
    const float* __restrict__ bias, int cSel, float* __restrict__ Cout, int N) {
    __shared__ float As[16 * 68];
    __shared__ float Ws[16 * 68];
    const float* A = (aSel == 0) ? g_A : (aSel == 1) ? g_A2 : g_co;
    float* C = (cSel == 0) ? g_gates : (cSel == 1) ? g_cop : Cout;

    int tid = threadIdx.x;
    int tx = tid & 15, ty = tid >> 4;
    int row = tid >> 2;          // 0..63
    int kk = (tid & 3) << 2;     // 0,4,8,12
    int n0 = blockIdx.x * 64;
    int kLen = K / gridDim.z;
    int kBeg = blockIdx.z * kLen;
    C += (size_t)blockIdx.z * 64 * N;

    F2 acc[4][2];
#pragma unroll
    for (int i = 0; i < 4; i++) { acc[i][0] = mkf2(0.f, 0.f); acc[i][1] = mkf2(0.f, 0.f); }

    int ng = n0 + row;
    for (int kc = kBeg; kc < kBeg + kLen; kc += 16) {
        float4 a4 = *(const float4*)(A + (size_t)row * K + kc + kk);
        float4 w4 = make_float4(0.f, 0.f, 0.f, 0.f);
        if (ng < N) {
            int kg = kc + kk;
            const float* wp = (kg < Ks) ? (W0 + (size_t)ng * Ks + kg)
                                        : (W1 + (size_t)ng * (K - Ks) + (kg - Ks));
            w4 = *(const float4*)wp;
        }
        As[(kk + 0) * 68 + row] = a4.x; As[(kk + 1) * 68 + row] = a4.y;
        As[(kk + 2) * 68 + row] = a4.z; As[(kk + 3) * 68 + row] = a4.w;
        Ws[(kk + 0) * 68 + row] = w4.x; Ws[(kk + 1) * 68 + row] = w4.y;
        Ws[(kk + 2) * 68 + row] = w4.z; Ws[(kk + 3) * 68 + row] = w4.w;
        __syncthreads();
        const float4* As4 = (const float4*)As;
        const float4* Ws4 = (const float4*)Ws;
#pragma unroll
        for (int k = 0; k < 16; k++) {
            float4 av = As4[k * 17 + ty];
            float4 bv = Ws4[k * 17 + tx];
            F2 b01 = mkf2(bv.x, bv.y), b23 = mkf2(bv.z, bv.w);
            F2 a0 = mkf2(av.x, av.x), a1 = mkf2(av.y, av.y);
            F2 a2 = mkf2(av.z, av.z), a3 = mkf2(av.w, av.w);
            fma2(acc[0][0], a0, b01); fma2(acc[0][1], a0, b23);
            fma2(acc[1][0], a1, b01); fma2(acc[1][1], a1, b23);
            fma2(acc[2][0], a2, b01); fma2(acc[2][1], a2, b23);
            fma2(acc[3][0], a3, b01); fma2(acc[3][1], a3, b23);
        }
        __syncthreads();
    }
#pragma unroll
    for (int i = 0; i < 4; i++) {
        int m = ty * 4 + i;
        float v[4];
        v[0] = acc[i][0].x; v[1] = acc[i][0].y;
        v[2] = acc[i][1].x; v[3] = acc[i][1].y;
#pragma unroll
        for (int j = 0; j < 4; j++) {
            int n = n0 + tx * 4 + j;
            if (n < N) {
                float o = v[j];
                if (bias && blockIdx.z == 0) o += bias[n];
                C[(size_t)m * N + n] = o;
            }
        }
    }
}

// ---------------- 2) LSTM activations ----------------
__global__ void lstm_act_kernel(const float* __restrict__ c0,
                                const float* __restrict__ b_ih,
                                const float* __restrict__ b_hh,
                                float* __restrict__ out_h,
                                float* __restrict__ out_c) {
    int b = blockIdx.x;
    const float* g0 = g_gates + (size_t)b * 4096;
    const float* g1 = g_gates + (size_t)64 * 4096 + (size_t)b * 4096;
#pragma unroll
    for (int r = 0; r < 4; r++) {
        int hid = threadIdx.x + r * 256;
        float gi = g0[hid] + g1[hid] + b_ih[hid] + b_hh[hid];
        float gf = g0[1024 + hid] + g1[1024 + hid] + b_ih[1024 + hid] + b_hh[1024 + hid];
        float gg = g0[2048 + hid] + g1[2048 + hid] + b_ih[2048 + hid] + b_hh[2048 + hid];
        float go = g0[3072 + hid] + g1[3072 + hid] + b_ih[3072 + hid] + b_hh[3072 + hid];
        float cc0 = c0[(size_t)b * H + hid];
        float si = 1.f / (1.f + __expf(-gi));
        float sf = 1.f / (1.f + __expf(-gf));
        float so = 1.f / (1.f + __expf(-go));
        float c = sf * cc0 + si * tanhf(gg);
        float h = so * tanhf(c);
        g_h[(size_t)b * H + hid] = h;
        out_h[(size_t)b * H + hid] = h;
        out_c[(size_t)b * H + hid] = c;
    }
}

// ---------------- 3) flash-style attention partials ----------------
// grid (8 chunks, 64 batches), 256 threads. Each block: 256 s-values of one batch.
// Single HBM pass over encoder_outputs: dot-product warps load each enc row,
// context accumulation re-reads it from L1. Online softmax with register context.
__global__ __launch_bounds__(256) void attn_partial_kernel(const float* __restrict__ enc) {
    __shared__ float h_s[1024];
    __shared__ float e_tile[32];
    int b = blockIdx.y, chunk = blockIdx.x;
    int tid = threadIdx.x, lane = tid & 31, w = tid >> 5;
    int s0 = chunk * 256;
    ((float4*)h_s)[tid] = ((const float4*)(g_h + (size_t)b * H))[tid];
    __syncthreads();
    float m = -INFINITY, l = 0.f;
    float cx0 = 0.f, cx1 = 0.f, cx2 = 0.f, cx3 = 0.f;
    for (int sub = 0; sub < 8; sub++) {
#pragma unroll
        for (int q = 0; q < 4; q++) {
            int sl = sub * 32 + w * 4 + q;
            const float* ep = enc + ((size_t)(s0 + sl) * 64 + b) * 1024;
            float sum = 0.f;
#pragma unroll
            for (int i = 0; i < 8; i++) {
                float4 ev = *(const float4*)(ep + i * 128 + lane * 4);
                float4 hv = *(const float4*)(h_s + i * 128 + lane * 4);
                sum += ev.x * hv.x + ev.y * hv.y + ev.z * hv.z + ev.w * hv.w;
            }
#pragma unroll
            for (int off = 16; off; off >>= 1) sum += __shfl_xor_sync(0xffffffffu, sum, off);
            if (lane == 0) {
                e_tile[w * 4 + q] = sum;
                g_e[(size_t)b * S + s0 + sl] = sum;
            }
        }
        __syncthreads();
        float tm = -INFINITY;
#pragma unroll
        for (int si = 0; si < 32; si++) tm = fmaxf(tm, e_tile[si]);
        float nm = fmaxf(m, tm);
        float sc = __expf(m - nm);   // m = -inf on first tile -> 0
        l *= sc; cx0 *= sc; cx1 *= sc; cx2 *= sc; cx3 *= sc;
        for (int si = 0; si < 32; si++) {
            float wt = __expf(e_tile[si] - nm);
            l += wt;
            const float* ep = enc + ((size_t)(s0 + sub * 32 + si) * 64 + b) * 1024;
            cx0 += wt * ep[tid];
            cx1 += wt * ep[tid + 256];
            cx2 += wt * ep[tid + 512];
            cx3 += wt * ep[tid + 768];
        }
        m = nm;
        __syncthreads();
    }
    int p = b * 8 + chunk;
    if (tid == 0) { g_pm[p] = m; g_pl[p] = l; }
    float* pc = g_pctx + (size_t)p * 1024;
    pc[tid] = cx0; pc[tid + 256] = cx1; pc[tid + 512] = cx2; pc[tid + 768] = cx3;
}

// ---------------- 4) combine partials: context, attn output, A2=[h||ctx] ----------------
__global__ void attn_combine_kernel(float* __restrict__ out_attn) {
    int b = blockIdx.x, tid = threadIdx.x;
    float M = -INFINITY;
#pragma unroll
    for (int i = 0; i < 8; i++) M = fmaxf(M, g_pm[b * 8 + i]);
    float L = 0.f;
    float em[8];
#pragma unroll
    for (int i = 0; i < 8; i++) {
        em[i] = __expf(g_pm[b * 8 + i] - M);
        L += g_pl[b * 8 + i] * em[i];
    }
    float invL = 1.f / L;
#pragma unroll
    for (int r = 0; r < 4; r++) {
        int j = tid + r * 256;
        float v = 0.f;
#pragma unroll
        for (int i = 0; i < 8; i++) v += em[i] * g_pctx[(size_t)(b * 8 + i) * 1024 + j];
        v *= invL;
        g_A2[(size_t)b * 2048 + 1024 + j] = v;
        g_A2[(size_t)b * 2048 + j] = g_h[(size_t)b * H + j];
    }
    for (int s = tid; s < S; s += 256)
        out_attn[(size_t)b * S + s] = __expf(g_e[(size_t)b * S + s] - M) * invL;
}

// ---------------- 5) concat GEMM finalize: sum split-K partials + bias + tanh ----------------
__global__ void concat_fin_kernel(const float* __restrict__ cb) {
    int b = blockIdx.x, tid = threadIdx.x;
#pragma unroll
    for (int r = 0; r < 4; r++) {
        int j = tid + r * 256;
        float v = cb[j];
#pragma unroll
        for (int z = 0; z < 8; z++)
            v += g_cop[(size_t)z * 64 * 1024 + (size_t)b * 1024 + j];
        g_co[(size_t)b * 1024 + j] = tanhf(v);
    }
}

// ---------------- launch ----------------
extern "C" void kernel_launch(void* const* d_in, const int* in_sizes, int n_in,
                              void* d_out, int out_size) {
    const int* seq = (const int*)d_in[0];
    const float* h0 = (const float*)d_in[1];
    const float* c0 = (const float*)d_in[2];
    const float* enc = (const float*)d_in[3];
    const float* embW = (const float*)d_in[4];
    const float* W_ih = (const float*)d_in[5];
    const float* W_hh = (const float*)d_in[6];
    const float* b_ih = (const float*)d_in[7];
    const float* b_hh = (const float*)d_in[8];
    const float* cW = (const float*)d_in[9];
    const float* cb = (const float*)d_in[10];
    const float* oW = (const float*)d_in[11];
    const float* ob = (const float*)d_in[12];

    float* out = (float*)d_out;
    float* out_logits = out;                       // [64, 50257]
    float* out_h = out + (size_t)B * VOCAB;        // [64, 1024]
    float* out_c = out_h + (size_t)B * H;          // [64, 1024]
    float* out_attn = out_c + (size_t)B * H;       // [64, 2048]

    // 1) A = [emb[seq] || h0]
    prep_kernel<<<64, 256>>>(seq, embW, h0);
    // 2) gates partials: [64,4096] = A[64,2048] @ [W_ih|W_hh]^T, split-K=2
    gemm_kernel<<<dim3(64, 1, 2), 256>>>(0, 2048, 1024, W_ih, W_hh, nullptr, 0, nullptr, 4096);
    // 3) LSTM activations -> h, c
    lstm_act_kernel<<<64, 256>>>(c0, b_ih, b_hh, out_h, out_c);
    // 4) attention: one pass over encoder_outputs
    attn_partial_kernel<<<dim3(8, 64), 256>>>(enc);
    attn_combine_kernel<<<64, 256>>>(out_attn);
    // 5) concat GEMM: [64,1024] = A2[64,2048] @ concat_W^T, split-K=8
    gemm_kernel<<<dim3(16, 1, 8), 256>>>(1, 2048, 2048, cW, nullptr, nullptr, 1, nullptr, 1024);
    concat_fin_kernel<<<64, 256>>>(cb);
    // 6) output GEMM: [64,50257] = co[64,1024] @ out_W^T + out_b
    gemm_kernel<<<dim3((VOCAB + 63) / 64, 1, 1), 256>>>(2, 1024, 1024, oW, nullptr, ob,
                                                        2, out_logits, VOCAB);
}

// round 5
// speedup vs baseline: 1.0424x; 1.0424x over previous
#include <cuda_runtime.h>
#include <cstdint>
#include <cstddef>
#include <cmath>

#define DINLINE __device__ __forceinline__

static constexpr int B = 64, H = 1024, E = 1024, S = 2048, VOCAB = 50257;
static constexpr int CH = 16;           // attention S-chunks

// ---------------- scratch (__device__ globals: allocation-free) ----------------
__device__ float g_A[B * 2048];            // [x || h0]  [64, 2048]
__device__ float g_gates[4 * B * 4096];    // split-K=4 partials of gates
__device__ float g_h[B * H];               // LSTM output h
__device__ float g_e[B * S];               // raw attention energies
__device__ float g_pm[B * CH];             // per-chunk running max
__device__ float g_pl[B * CH];             // per-chunk running sum
__device__ float g_pctx[B * CH * H];       // per-chunk unnormalized context
__device__ float g_A2[B * 2048];           // [h || context]
__device__ float g_cop[8 * B * H];         // split-K=8 partials of concat GEMM
__device__ float g_co[B * H];              // tanh(concat)

// ---------------- packed f32x2 helpers (with scalar fallback) ----------------
struct F2 { float x, y; };
DINLINE F2 mkf2(float a, float b) { F2 r; r.x = a; r.y = b; return r; }

#if defined(__CUDA_ARCH__) && (__CUDA_ARCH__ >= 1000)
DINLINE void fma2(F2& d, F2 a, F2 b) {
    unsigned long long dd, aa, bb;
    asm("mov.b64 %0, {%1,%2};" : "=l"(aa) : "f"(a.x), "f"(a.y));
    asm("mov.b64 %0, {%1,%2};" : "=l"(bb) : "f"(b.x), "f"(b.y));
    asm("mov.b64 %0, {%1,%2};" : "=l"(dd) : "f"(d.x), "f"(d.y));
    asm("fma.rn.f32x2 %0, %1, %2, %0;" : "+l"(dd) : "l"(aa), "l"(bb));
    asm("mov.b64 {%0,%1}, %2;" : "=f"(d.x), "=f"(d.y) : "l"(dd));
}
#else
DINLINE void fma2(F2& d, F2 a, F2 b) {
    d.x = fmaf(a.x, b.x, d.x);
    d.y = fmaf(a.y, b.y, d.y);
}
#endif

// ---------------- 1) build A = [emb[seq] || h0] ----------------
__global__ void prep_kernel(const int* __restrict__ seq,
                            const float* __restrict__ embW,
                            const float* __restrict__ h0) {
    int b = blockIdx.x, t = threadIdx.x;
    const float4* er = (const float4*)(embW + (size_t)seq[b] * E);
    const float4* hr = (const float4*)(h0 + (size_t)b * H);
    float4* dst = (float4*)(g_A + (size_t)b * 2048);
    dst[t] = er[t];
    dst[256 + t] = hr[t];
}

// ---------------- generic M=64 GEMM: C = A[64,K] @ W[N,K]^T (+bias) ----------------
// Software-pipelined: 32-wide K-chunks, double-buffered smem, 1 barrier/chunk.
// aSel: 0->g_A, 1->g_A2, 2->g_co. cSel: 0->g_gates, 1->g_cop, 2->Cout.
// W(n,k) from W0 if k<Ks else W1. gridDim.z = split-K; partial z at C+z*64*N.
__global__ __launch_bounds__(256) void gemm_kernel(
    int aSel, int K, int Ks,
    const float* __restrict__ W0, const float* __restrict__ W1,
    const float* __restrict__ bias, int cSel, float* __restrict__ Cout, int N) {
    __shared__ float As[2][32 * 68];
    __shared__ float Ws[2][32 * 68];
    const float* A = (aSel == 0) ? g_A : (aSel == 1) ? g_A2 : g_co;
    float* C = (cSel == 0) ? g_gates : (cSel == 1) ? g_cop : Cout;

    int tid = threadIdx.x;
    int tx = tid & 15, ty = tid >> 4;
    int row = tid >> 2;          // 0..63
    int kk = (tid & 3) << 3;     // 0,8,16,24
    int n0 = blockIdx.x * 64;
    int kLen = K / gridDim.z;    // multiple of 32
    int kBeg = blockIdx.z * kLen;
    C += (size_t)blockIdx.z * 64 * N;
    int ng = n0 + row;
    bool wok = ng < N;

    float4 ar0, ar1, wr0, wr1;
#define LOADT(kc) do {                                                        \
        int kg = (kc) + kk;                                                   \
        const float* ap = A + (size_t)row * K + kg;                           \
        ar0 = *(const float4*)ap; ar1 = *(const float4*)(ap + 4);             \
        if (wok) {                                                            \
            const float* wp = (kg < Ks) ? (W0 + (size_t)ng * Ks + kg)         \
                                        : (W1 + (size_t)ng * (K - Ks) + (kg - Ks)); \
            wr0 = *(const float4*)wp; wr1 = *(const float4*)(wp + 4);         \
        } else { wr0 = make_float4(0.f,0.f,0.f,0.f); wr1 = wr0; }             \
    } while (0)

#define STORET(p) do {                                                        \
        float* as = As[p]; float* ws = Ws[p];                                 \
        as[(kk+0)*68+row]=ar0.x; as[(kk+1)*68+row]=ar0.y;                     \
        as[(kk+2)*68+row]=ar0.z; as[(kk+3)*68+row]=ar0.w;                     \
        as[(kk+4)*68+row]=ar1.x; as[(kk+5)*68+row]=ar1.y;                     \
        as[(kk+6)*68+row]=ar1.z; as[(kk+7)*68+row]=ar1.w;                     \
        ws[(kk+0)*68+row]=wr0.x; ws[(kk+1)*68+row]=wr0.y;                     \
        ws[(kk+2)*68+row]=wr0.z; ws[(kk+3)*68+row]=wr0.w;                     \
        ws[(kk+4)*68+row]=wr1.x; ws[(kk+5)*68+row]=wr1.y;                     \
        ws[(kk+6)*68+row]=wr1.z; ws[(kk+7)*68+row]=wr1.w;                     \
    } while (0)

    F2 acc[4][2];
#pragma unroll
    for (int i = 0; i < 4; i++) { acc[i][0] = mkf2(0.f, 0.f); acc[i][1] = mkf2(0.f, 0.f); }

    LOADT(kBeg);
    STORET(0);
    __syncthreads();

    int nChunk = kLen >> 5;
    for (int c = 0; c < nChunk; c++) {
        int p = c & 1;
        if (c + 1 < nChunk) LOADT(kBeg + (c + 1) * 32);   // prefetch next (latency hidden under FMAs)
        const float4* As4 = (const float4*)As[p];
        const float4* Ws4 = (const float4*)Ws[p];
#pragma unroll
        for (int k = 0; k < 32; k++) {
            float4 av = As4[k * 17 + ty];
            float4 bv = Ws4[k * 17 + tx];
            F2 b01 = mkf2(bv.x, bv.y), b23 = mkf2(bv.z, bv.w);
            F2 a0 = mkf2(av.x, av.x), a1 = mkf2(av.y, av.y);
            F2 a2 = mkf2(av.z, av.z), a3 = mkf2(av.w, av.w);
            fma2(acc[0][0], a0, b01); fma2(acc[0][1], a0, b23);
            fma2(acc[1][0], a1, b01); fma2(acc[1][1], a1, b23);
            fma2(acc[2][0], a2, b01); fma2(acc[2][1], a2, b23);
            fma2(acc[3][0], a3, b01); fma2(acc[3][1], a3, b23);
        }
        if (c + 1 < nChunk) STORET(p ^ 1);
        __syncthreads();
    }
#undef LOADT
#undef STORET

#pragma unroll
    for (int i = 0; i < 4; i++) {
        int m = ty * 4 + i;
        float v[4];
        v[0] = acc[i][0].x; v[1] = acc[i][0].y;
        v[2] = acc[i][1].x; v[3] = acc[i][1].y;
#pragma unroll
        for (int j = 0; j < 4; j++) {
            int n = n0 + tx * 4 + j;
            if (n < N) {
                float o = v[j];
                if (bias && blockIdx.z == 0) o += bias[n];
                C[(size_t)m * N + n] = o;
            }
        }
    }
}

// ---------------- 2) LSTM activations (sums 4 split-K partials) ----------------
__global__ void lstm_act_kernel(const float* __restrict__ c0,
                                const float* __restrict__ b_ih,
                                const float* __restrict__ b_hh,
                                float* __restrict__ out_h,
                                float* __restrict__ out_c) {
    int b = blockIdx.x;
#pragma unroll
    for (int r = 0; r < 4; r++) {
        int hid = threadIdx.x + r * 256;
        float gi = b_ih[hid] + b_hh[hid];
        float gf = b_ih[1024 + hid] + b_hh[1024 + hid];
        float gg = b_ih[2048 + hid] + b_hh[2048 + hid];
        float go = b_ih[3072 + hid] + b_hh[3072 + hid];
#pragma unroll
        for (int z = 0; z < 4; z++) {
            const float* gp = g_gates + (size_t)z * 64 * 4096 + (size_t)b * 4096;
            gi += gp[hid];
            gf += gp[1024 + hid];
            gg += gp[2048 + hid];
            go += gp[3072 + hid];
        }
        float cc0 = c0[(size_t)b * H + hid];
        float si = 1.f / (1.f + __expf(-gi));
        float sf = 1.f / (1.f + __expf(-gf));
        float so = 1.f / (1.f + __expf(-go));
        float c = sf * cc0 + si * tanhf(gg);
        float h = so * tanhf(c);
        g_h[(size_t)b * H + hid] = h;
        out_h[(size_t)b * H + hid] = h;
        out_c[(size_t)b * H + hid] = c;
    }
}

// ---------------- 3) flash-style attention partials ----------------
// grid (CH=16 chunks, 64 batches), 256 threads: 128 s-values per block.
// Single HBM pass; online softmax; context in registers.
__global__ __launch_bounds__(256) void attn_partial_kernel(const float* __restrict__ enc) {
    __shared__ float h_s[1024];
    __shared__ float e_tile[32];
    int b = blockIdx.y, chunk = blockIdx.x;
    int tid = threadIdx.x, lane = tid & 31, w = tid >> 5;
    int s0 = chunk * (S / CH);     // 128 rows per chunk
    ((float4*)h_s)[tid] = ((const float4*)(g_h + (size_t)b * H))[tid];
    __syncthreads();
    float m = -INFINITY, l = 0.f;
    float cx0 = 0.f, cx1 = 0.f, cx2 = 0.f, cx3 = 0.f;
    for (int sub = 0; sub < (S / CH) / 32; sub++) {
#pragma unroll
        for (int q = 0; q < 4; q++) {
            int sl = sub * 32 + w * 4 + q;
            const float* ep = enc + ((size_t)(s0 + sl) * 64 + b) * 1024;
            float sum = 0.f;
#pragma unroll
            for (int i = 0; i < 8; i++) {
                float4 ev = *(const float4*)(ep + i * 128 + lane * 4);
                float4 hv = *(const float4*)(h_s + i * 128 + lane * 4);
                sum += ev.x * hv.x + ev.y * hv.y + ev.z * hv.z + ev.w * hv.w;
            }
#pragma unroll
            for (int off = 16; off; off >>= 1) sum += __shfl_xor_sync(0xffffffffu, sum, off);
            if (lane == 0) {
                e_tile[w * 4 + q] = sum;
                g_e[(size_t)b * S + s0 + sl] = sum;
            }
        }
        __syncthreads();
        float tm = -INFINITY;
#pragma unroll
        for (int si = 0; si < 32; si++) tm = fmaxf(tm, e_tile[si]);
        float nm = fmaxf(m, tm);
        float sc = __expf(m - nm);   // m = -inf first tile -> 0
        l *= sc; cx0 *= sc; cx1 *= sc; cx2 *= sc; cx3 *= sc;
        for (int si = 0; si < 32; si++) {
            float wt = __expf(e_tile[si] - nm);
            l += wt;
            const float* ep = enc + ((size_t)(s0 + sub * 32 + si) * 64 + b) * 1024;
            cx0 += wt * ep[tid];
            cx1 += wt * ep[tid + 256];
            cx2 += wt * ep[tid + 512];
            cx3 += wt * ep[tid + 768];
        }
        m = nm;
        __syncthreads();
    }
    int p = b * CH + chunk;
    if (tid == 0) { g_pm[p] = m; g_pl[p] = l; }
    float* pc = g_pctx + (size_t)p * 1024;
    pc[tid] = cx0; pc[tid + 256] = cx1; pc[tid + 512] = cx2; pc[tid + 768] = cx3;
}

// ---------------- 4) combine partials: context, attn output, A2=[h||ctx] ----------------
__global__ void attn_combine_kernel(float* __restrict__ out_attn) {
    int b = blockIdx.x, tid = threadIdx.x;
    float M = -INFINITY;
#pragma unroll
    for (int i = 0; i < CH; i++) M = fmaxf(M, g_pm[b * CH + i]);
    float L = 0.f;
    float em[CH];
#pragma unroll
    for (int i = 0; i < CH; i++) {
        em[i] = __expf(g_pm[b * CH + i] - M);
        L += g_pl[b * CH + i] * em[i];
    }
    float invL = 1.f / L;
#pragma unroll
    for (int r = 0; r < 4; r++) {
        int j = tid + r * 256;
        float v = 0.f;
#pragma unroll
        for (int i = 0; i < CH; i++) v += em[i] * g_pctx[(size_t)(b * CH + i) * 1024 + j];
        v *= invL;
        g_A2[(size_t)b * 2048 + 1024 + j] = v;
        g_A2[(size_t)b * 2048 + j] = g_h[(size_t)b * H + j];
    }
    for (int s = tid; s < S; s += 256)
        out_attn[(size_t)b * S + s] = __expf(g_e[(size_t)b * S + s] - M) * invL;
}

// ---------------- 5) concat GEMM finalize: sum split-K partials + bias + tanh ----------------
__global__ void concat_fin_kernel(const float* __restrict__ cb) {
    int b = blockIdx.x, tid = threadIdx.x;
#pragma unroll
    for (int r = 0; r < 4; r++) {
        int j = tid + r * 256;
        float v = cb[j];
#pragma unroll
        for (int z = 0; z < 8; z++)
            v += g_cop[(size_t)z * 64 * 1024 + (size_t)b * 1024 + j];
        g_co[(size_t)b * 1024 + j] = tanhf(v);
    }
}

// ---------------- launch ----------------
extern "C" void kernel_launch(void* const* d_in, const int* in_sizes, int n_in,
                              void* d_out, int out_size) {
    const int* seq = (const int*)d_in[0];
    const float* h0 = (const float*)d_in[1];
    const float* c0 = (const float*)d_in[2];
    const float* enc = (const float*)d_in[3];
    const float* embW = (const float*)d_in[4];
    const float* W_ih = (const float*)d_in[5];
    const float* W_hh = (const float*)d_in[6];
    const float* b_ih = (const float*)d_in[7];
    const float* b_hh = (const float*)d_in[8];
    const float* cW = (const float*)d_in[9];
    const float* cb = (const float*)d_in[10];
    const float* oW = (const float*)d_in[11];
    const float* ob = (const float*)d_in[12];

    float* out = (float*)d_out;
    float* out_logits = out;                       // [64, 50257]
    float* out_h = out + (size_t)B * VOCAB;        // [64, 1024]
    float* out_c = out_h + (size_t)B * H;          // [64, 1024]
    float* out_attn = out_c + (size_t)B * H;       // [64, 2048]

    // 1) A = [emb[seq] || h0]
    prep_kernel<<<64, 256>>>(seq, embW, h0);
    // 2) gates partials: [64,4096] = A[64,2048] @ [W_ih|W_hh]^T, split-K=4
    gemm_kernel<<<dim3(64, 1, 4), 256>>>(0, 2048, 1024, W_ih, W_hh, nullptr, 0, nullptr, 4096);
    // 3) LSTM activations -> h, c
    lstm_act_kernel<<<64, 256>>>(c0, b_ih, b_hh, out_h, out_c);
    // 4) attention: one pass over encoder_outputs
    attn_partial_kernel<<<dim3(CH, 64), 256>>>(enc);
    attn_combine_kernel<<<64, 256>>>(out_attn);
    // 5) concat GEMM: [64,1024] = A2[64,2048] @ concat_W^T, split-K=8
    gemm_kernel<<<dim3(16, 1, 8), 256>>>(1, 2048, 2048, cW, nullptr, nullptr, 1, nullptr, 1024);
    concat_fin_kernel<<<64, 256>>>(cb);
    // 6) output GEMM: [64,50257] = co[64,1024] @ out_W^T + out_b
    gemm_kernel<<<dim3((VOCAB + 63) / 64, 1, 1), 256>>>(2, 1024, 1024, oW, nullptr, ob,
                                                        2, out_logits, VOCAB);
}

// round 6
// speedup vs baseline: 1.5198x; 1.4580x over previous
#include <cuda_runtime.h>
#include <cuda_bf16.h>
#include <cstdint>
#include <cstddef>
#include <cmath>

#define DINLINE __device__ __forceinline__

static constexpr int B = 64, H = 1024, E = 1024, S = 2048, VOCAB = 50257;
static constexpr int CH = 16;           // attention S-chunks (128 rows each)

// ---------------- scratch (__device__ globals: allocation-free) ----------------
__device__ float g_A[B * 2048];            // [x || h0]
__device__ float g_gates[4 * B * 4096];    // split-K=4 partials of gates
__device__ float g_h[B * H];               // LSTM output h
__device__ float g_e[B * S];               // raw attention energies
__device__ float g_pm[B * CH];             // per-chunk running max
__device__ float g_pl[B * CH];             // per-chunk running sum
__device__ float g_pctx[B * CH * H];       // per-chunk unnormalized context
__device__ float g_A2[B * 2048];           // [h || context]
__device__ float g_cop[8 * B * H];         // split-K=8 partials of concat GEMM
__device__ unsigned short g_coh[B * H];    // bf16 hi of tanh(concat)
__device__ unsigned short g_col[B * H];    // bf16 lo of tanh(concat)

// ---------------- helpers ----------------
DINLINE void cp16(void* smem_ptr, const void* gptr) {
    uint32_t s = (uint32_t)__cvta_generic_to_shared(smem_ptr);
    asm volatile("cp.async.cg.shared.global [%0], [%1], 16;" :: "r"(s), "l"(gptr) : "memory");
}
DINLINE void cp_commit() { asm volatile("cp.async.commit_group;" ::: "memory"); }
DINLINE void cp_wait1() { asm volatile("cp.async.wait_group 1;" ::: "memory"); }
DINLINE void cp_wait0() { asm volatile("cp.async.wait_group 0;" ::: "memory"); }

DINLINE void mma_bf16(float* c, uint32_t a0, uint32_t a1, uint32_t a2, uint32_t a3,
                      uint32_t b0, uint32_t b1) {
    asm volatile(
        "mma.sync.aligned.m16n8k16.row.col.f32.bf16.bf16.f32 "
        "{%0,%1,%2,%3}, {%4,%5,%6,%7}, {%8,%9}, {%0,%1,%2,%3};"
        : "+f"(c[0]), "+f"(c[1]), "+f"(c[2]), "+f"(c[3])
        : "r"(a0), "r"(a1), "r"(a2), "r"(a3), "r"(b0), "r"(b1));
}

// ---------------- 1) build A = [emb[seq] || h0] ----------------
__global__ void prep_kernel(const int* __restrict__ seq,
                            const float* __restrict__ embW,
                            const float* __restrict__ h0) {
    int b = blockIdx.x, t = threadIdx.x;
    const float4* er = (const float4*)(embW + (size_t)seq[b] * E);
    const float4* hr = (const float4*)(h0 + (size_t)b * H);
    float4* dst = (float4*)(g_A + (size_t)b * 2048);
    dst[t] = er[t];
    dst[256 + t] = hr[t];
}

// ---------------- fp32 GEMM for gates/concat: C = A[64,K] @ W[N,K]^T ----------------
// aSel: 0->g_A, 1->g_A2. cSel: 0->g_gates, 1->g_cop.
// W(n,k) from W0 if k<Ks else W1. gridDim.z = split-K; partial z at C+z*64*N.
__global__ __launch_bounds__(256) void gemm_kernel(
    int aSel, int K, int Ks,
    const float* __restrict__ W0, const float* __restrict__ W1,
    int cSel, int N) {
    __shared__ float As[2][32 * 68];
    __shared__ float Ws[2][32 * 68];
    const float* A = (aSel == 0) ? g_A : g_A2;
    float* C = (cSel == 0) ? g_gates : g_cop;

    int tid = threadIdx.x;
    int tx = tid & 15, ty = tid >> 4;
    int row = tid >> 2;
    int kk = (tid & 3) << 3;
    int n0 = blockIdx.x * 64;
    int kLen = K / gridDim.z;
    int kBeg = blockIdx.z * kLen;
    C += (size_t)blockIdx.z * 64 * N;
    int ng = n0 + row;
    bool wok = ng < N;

    float4 ar0, ar1, wr0, wr1;
#define LOADT(kc) do {                                                        \
        int kg = (kc) + kk;                                                   \
        const float* ap = A + (size_t)row * K + kg;                           \
        ar0 = *(const float4*)ap; ar1 = *(const float4*)(ap + 4);             \
        if (wok) {                                                            \
            const float* wp = (kg < Ks) ? (W0 + (size_t)ng * Ks + kg)         \
                                        : (W1 + (size_t)ng * (K - Ks) + (kg - Ks)); \
            wr0 = *(const float4*)wp; wr1 = *(const float4*)(wp + 4);         \
        } else { wr0 = make_float4(0.f,0.f,0.f,0.f); wr1 = wr0; }             \
    } while (0)
#define STORET(p) do {                                                        \
        float* as = As[p]; float* ws = Ws[p];                                 \
        as[(kk+0)*68+row]=ar0.x; as[(kk+1)*68+row]=ar0.y;                     \
        as[(kk+2)*68+row]=ar0.z; as[(kk+3)*68+row]=ar0.w;                     \
        as[(kk+4)*68+row]=ar1.x; as[(kk+5)*68+row]=ar1.y;                     \
        as[(kk+6)*68+row]=ar1.z; as[(kk+7)*68+row]=ar1.w;                     \
        ws[(kk+0)*68+row]=wr0.x; ws[(kk+1)*68+row]=wr0.y;                     \
        ws[(kk+2)*68+row]=wr0.z; ws[(kk+3)*68+row]=wr0.w;                     \
        ws[(kk+4)*68+row]=wr1.x; ws[(kk+5)*68+row]=wr1.y;                     \
        ws[(kk+6)*68+row]=wr1.z; ws[(kk+7)*68+row]=wr1.w;                     \
    } while (0)

    float acc[4][4];
#pragma unroll
    for (int i = 0; i < 4; i++)
#pragma unroll
        for (int j = 0; j < 4; j++) acc[i][j] = 0.f;

    LOADT(kBeg);
    STORET(0);
    __syncthreads();

    int nChunk = kLen >> 5;
    for (int c = 0; c < nChunk; c++) {
        int p = c & 1;
        if (c + 1 < nChunk) LOADT(kBeg + (c + 1) * 32);
        const float4* As4 = (const float4*)As[p];
        const float4* Ws4 = (const float4*)Ws[p];
#pragma unroll
        for (int k = 0; k < 32; k++) {
            float4 av = As4[k * 17 + ty];
            float4 bv = Ws4[k * 17 + tx];
#pragma unroll
            for (int i = 0; i < 4; i++) {
                float a = (i == 0) ? av.x : (i == 1) ? av.y : (i == 2) ? av.z : av.w;
                acc[i][0] = fmaf(a, bv.x, acc[i][0]);
                acc[i][1] = fmaf(a, bv.y, acc[i][1]);
                acc[i][2] = fmaf(a, bv.z, acc[i][2]);
                acc[i][3] = fmaf(a, bv.w, acc[i][3]);
            }
        }
        if (c + 1 < nChunk) STORET(p ^ 1);
        __syncthreads();
    }
#undef LOADT
#undef STORET

#pragma unroll
    for (int i = 0; i < 4; i++) {
        int m = ty * 4 + i;
#pragma unroll
        for (int j = 0; j < 4; j++) {
            int n = n0 + tx * 4 + j;
            if (n < N) C[(size_t)m * N + n] = acc[i][j];
        }
    }
}

// ---------------- 2) LSTM activations (sums 4 split-K partials) ----------------
__global__ void lstm_act_kernel(const float* __restrict__ c0,
                                const float* __restrict__ b_ih,
                                const float* __restrict__ b_hh,
                                float* __restrict__ out_h,
                                float* __restrict__ out_c) {
    int b = blockIdx.x;
#pragma unroll
    for (int r = 0; r < 4; r++) {
        int hid = threadIdx.x + r * 256;
        float gi = b_ih[hid] + b_hh[hid];
        float gf = b_ih[1024 + hid] + b_hh[1024 + hid];
        float gg = b_ih[2048 + hid] + b_hh[2048 + hid];
        float go = b_ih[3072 + hid] + b_hh[3072 + hid];
#pragma unroll
        for (int z = 0; z < 4; z++) {
            const float* gp = g_gates + (size_t)z * 64 * 4096 + (size_t)b * 4096;
            gi += gp[hid];
            gf += gp[1024 + hid];
            gg += gp[2048 + hid];
            go += gp[3072 + hid];
        }
        float cc0 = c0[(size_t)b * H + hid];
        float si = 1.f / (1.f + __expf(-gi));
        float sf = 1.f / (1.f + __expf(-gf));
        float so = 1.f / (1.f + __expf(-go));
        float c = sf * cc0 + si * tanhf(gg);
        float h = so * tanhf(c);
        g_h[(size_t)b * H + hid] = h;
        out_h[(size_t)b * H + hid] = h;
        out_c[(size_t)b * H + hid] = c;
    }
}

// ---------------- 3) smem-staged flash attention ----------------
// grid (CH, B), 256 threads. Each block: 128 s-rows of one batch, in 8 tiles of 16.
// cp.async double-buffered: enc read from DRAM exactly once; dots AND context
// both consume the smem copy (no L1-capacity dependence).
__global__ __launch_bounds__(256) void attn_staged_kernel(const float* __restrict__ enc) {
    extern __shared__ float smf[];
    float* buf0 = smf;                 // 16*1024
    float* buf1 = smf + 16 * 1024;     // 16*1024
    float* h_s = smf + 32 * 1024;      // 1024
    __shared__ float e_tile[16];

    int b = blockIdx.y, chunk = blockIdx.x;
    int tid = threadIdx.x, lane = tid & 31, w = tid >> 5;
    int s0 = chunk * (S / CH);
    int cr = tid >> 4, cc = tid & 15;  // cp.async mapping: row, col16

    ((float4*)h_s)[tid] = ((const float4*)(g_h + (size_t)b * H))[tid];

#define ISSUE_TILE(t, dst) do {                                                   \
        const float* gsrc = enc + ((size_t)(s0 + (t) * 16 + cr) * 64 + b) * 1024; \
        _Pragma("unroll")                                                         \
        for (int j = 0; j < 16; j++) {                                            \
            int f4 = cc + j * 16;                                                 \
            cp16((dst) + cr * 1024 + f4 * 4, gsrc + f4 * 4);                      \
        }                                                                         \
        cp_commit();                                                              \
    } while (0)

    ISSUE_TILE(0, buf0);

    float m = -INFINITY, l = 0.f;
    float cx0 = 0.f, cx1 = 0.f, cx2 = 0.f, cx3 = 0.f;

    for (int t = 0; t < 8; t++) {
        float* bufc = (t & 1) ? buf1 : buf0;
        if (t < 7) {
            ISSUE_TILE(t + 1, (t & 1) ? buf0 : buf1);
            cp_wait1();
        } else {
            cp_wait0();
        }
        __syncthreads();

        // dots: warp w computes rows 2w, 2w+1 of this 16-row tile (from smem)
#pragma unroll
        for (int q = 0; q < 2; q++) {
            int r = w * 2 + q;
            const float* rp = bufc + r * 1024;
            float sum = 0.f;
#pragma unroll
            for (int i = 0; i < 8; i++) {
                float4 ev = *(const float4*)(rp + i * 128 + lane * 4);
                float4 hv = *(const float4*)(h_s + i * 128 + lane * 4);
                sum += ev.x * hv.x + ev.y * hv.y + ev.z * hv.z + ev.w * hv.w;
            }
#pragma unroll
            for (int off = 16; off; off >>= 1) sum += __shfl_xor_sync(0xffffffffu, sum, off);
            if (lane == 0) {
                e_tile[r] = sum;
                g_e[(size_t)b * S + s0 + t * 16 + r] = sum;
            }
        }
        __syncthreads();

        // online softmax + context accumulate (from smem)
        float tm = -INFINITY;
#pragma unroll
        for (int si = 0; si < 16; si++) tm = fmaxf(tm, e_tile[si]);
        float nm = fmaxf(m, tm);
        float sc = __expf(m - nm);     // 0 on first tile
        l *= sc; cx0 *= sc; cx1 *= sc; cx2 *= sc; cx3 *= sc;
#pragma unroll
        for (int si = 0; si < 16; si++) {
            float wt = __expf(e_tile[si] - nm);
            l += wt;
            const float* rp = bufc + si * 1024 + tid;
            cx0 += wt * rp[0];
            cx1 += wt * rp[256];
            cx2 += wt * rp[512];
            cx3 += wt * rp[768];
        }
        m = nm;
        __syncthreads();   // all reads done before next iteration's cp.async overwrites
    }
#undef ISSUE_TILE

    int p = b * CH + chunk;
    if (tid == 0) { g_pm[p] = m; g_pl[p] = l; }
    float* pc = g_pctx + (size_t)p * 1024;
    pc[tid] = cx0; pc[tid + 256] = cx1; pc[tid + 512] = cx2; pc[tid + 768] = cx3;
}

// ---------------- 4) combine partials: context, attn output, A2=[h||ctx] ----------------
__global__ void attn_combine_kernel(float* __restrict__ out_attn) {
    int b = blockIdx.x, tid = threadIdx.x;
    float M = -INFINITY;
#pragma unroll
    for (int i = 0; i < CH; i++) M = fmaxf(M, g_pm[b * CH + i]);
    float L = 0.f;
    float em[CH];
#pragma unroll
    for (int i = 0; i < CH; i++) {
        em[i] = __expf(g_pm[b * CH + i] - M);
        L += g_pl[b * CH + i] * em[i];
    }
    float invL = 1.f / L;
#pragma unroll
    for (int r = 0; r < 4; r++) {
        int j = tid + r * 256;
        float v = 0.f;
#pragma unroll
        for (int i = 0; i < CH; i++) v += em[i] * g_pctx[(size_t)(b * CH + i) * 1024 + j];
        v *= invL;
        g_A2[(size_t)b * 2048 + 1024 + j] = v;
        g_A2[(size_t)b * 2048 + j] = g_h[(size_t)b * H + j];
    }
    for (int s = tid; s < S; s += 256)
        out_attn[(size_t)b * S + s] = __expf(g_e[(size_t)b * S + s] - M) * invL;
}

// ---------------- 5) concat finalize: sum partials + bias + tanh -> bf16 hi/lo ----------------
__global__ void concat_fin_kernel(const float* __restrict__ cb) {
    int b = blockIdx.x, tid = threadIdx.x;
#pragma unroll
    for (int r = 0; r < 4; r++) {
        int j = tid + r * 256;
        float v = cb[j];
#pragma unroll
        for (int z = 0; z < 8; z++)
            v += g_cop[(size_t)z * 64 * 1024 + (size_t)b * 1024 + j];
        v = tanhf(v);
        __nv_bfloat16 hh = __float2bfloat16_rn(v);
        float lo = v - __bfloat162float(hh);
        g_coh[(size_t)b * 1024 + j] = __bfloat16_as_ushort(hh);
        g_col[(size_t)b * 1024 + j] = __bfloat16_as_ushort(__float2bfloat16_rn(lo));
    }
}

// ---------------- 6) output GEMM via bf16 hi/lo split tensor cores ----------------
// logits[64, VOCAB] = co[64,1024] @ oW[VOCAB,1024]^T + ob
// C = Ah*Bh + Ah*Bl + Al*Bh (fp32 accum). N-tile 128, K-chunk 32, double-buffered.
static constexpr int OG_PAD = 40;       // halves per smem row (conflict-free)
static constexpr int OG_BUF = 15360;    // halves per buffer
// per-buffer layout (halves): Whi[128*40]=0, Wlo=5120, Ahi[64*40]=10240, Alo=12800
__global__ __launch_bounds__(256) void out_gemm_kernel(
    const float* __restrict__ oW, const float* __restrict__ ob,
    float* __restrict__ out) {
    extern __shared__ unsigned short smh[];
    const int tid = threadIdx.x, lane = tid & 31, w = tid >> 5;
    const int g = lane >> 2, tq = lane & 3;
    const int n0 = blockIdx.x * 128;

    // W loader mapping: thread -> (row 0..127, k-half 0/16)
    const int wn = tid >> 1;
    const int wkh = (tid & 1) * 16;
    const int gn = n0 + wn;
    const bool wvalid = gn < VOCAB;
    const float* wbase = oW + (size_t)gn * 1024 + wkh;

    const uint32_t* AhU = (const uint32_t*)g_coh;
    const uint32_t* AlU = (const uint32_t*)g_col;

    float4 wr[4];
    uint32_t ahr[4], alr[4];

#define OG_LOAD(c) do {                                                       \
        int kc = (c) * 32;                                                    \
        if (wvalid) {                                                         \
            const float* p_ = wbase + kc;                                     \
            wr[0] = *(const float4*)p_;       wr[1] = *(const float4*)(p_ + 4);  \
            wr[2] = *(const float4*)(p_ + 8); wr[3] = *(const float4*)(p_ + 12); \
        } else {                                                              \
            wr[0] = make_float4(0.f,0.f,0.f,0.f); wr[1]=wr[0]; wr[2]=wr[0]; wr[3]=wr[0]; \
        }                                                                     \
        int kp2 = kc >> 1;                                                    \
        _Pragma("unroll")                                                     \
        for (int j = 0; j < 4; j++) {                                         \
            int flat = tid + j * 256;                                         \
            int am = flat >> 4, ak = flat & 15;                               \
            ahr[j] = AhU[am * 512 + kp2 + ak];                                \
            alr[j] = AlU[am * 512 + kp2 + ak];                                \
        }                                                                     \
    } while (0)

#define OG_STORE(p) do {                                                      \
        unsigned short* Whi_ = smh + (p) * OG_BUF;                            \
        unsigned short* Wlo_ = Whi_ + 5120;                                   \
        unsigned short* Ahi_ = Whi_ + 10240;                                  \
        unsigned short* Alo_ = Whi_ + 12800;                                  \
        const float* wf = (const float*)wr;                                   \
        _Pragma("unroll")                                                     \
        for (int i = 0; i < 8; i++) {                                         \
            float v0 = wf[2*i], v1 = wf[2*i+1];                               \
            __nv_bfloat16 h0 = __float2bfloat16_rn(v0);                       \
            __nv_bfloat16 h1 = __float2bfloat16_rn(v1);                       \
            __nv_bfloat16 l0 = __float2bfloat16_rn(v0 - __bfloat162float(h0));\
            __nv_bfloat16 l1 = __float2bfloat16_rn(v1 - __bfloat162float(h1));\
            uint32_t hp = (uint32_t)__bfloat16_as_ushort(h0)                  \
                        | ((uint32_t)__bfloat16_as_ushort(h1) << 16);         \
            uint32_t lp = (uint32_t)__bfloat16_as_ushort(l0)                  \
                        | ((uint32_t)__bfloat16_as_ushort(l1) << 16);         \
            *(uint32_t*)&Whi_[wn * OG_PAD + wkh + 2*i] = hp;                  \
            *(uint32_t*)&Wlo_[wn * OG_PAD + wkh + 2*i] = lp;                  \
        }                                                                     \
        _Pragma("unroll")                                                     \
        for (int j = 0; j < 4; j++) {                                         \
            int flat = tid + j * 256;                                         \
            int am = flat >> 4, ak = flat & 15;                               \
            *(uint32_t*)&Ahi_[am * OG_PAD + 2*ak] = ahr[j];                   \
            *(uint32_t*)&Alo_[am * OG_PAD + 2*ak] = alr[j];                   \
        }                                                                     \
    } while (0)

    const int m0 = (w & 3) * 16;     // m-strip
    const int nc0 = (w >> 2) * 64;   // n-half within 128 tile
    float acc[8][4];
#pragma unroll
    for (int i = 0; i < 8; i++)
#pragma unroll
        for (int j = 0; j < 4; j++) acc[i][j] = 0.f;

    OG_LOAD(0);
    OG_STORE(0);
    __syncthreads();

    for (int c = 0; c < 32; c++) {
        int p = c & 1;
        if (c < 31) OG_LOAD(c + 1);
        const unsigned short* Whi = smh + p * OG_BUF;
        const unsigned short* Wlo = Whi + 5120;
        const unsigned short* Ahi = Whi + 10240;
        const unsigned short* Alo = Whi + 12800;
#pragma unroll
        for (int ks = 0; ks < 32; ks += 16) {
            uint32_t ah0 = *(const uint32_t*)&Ahi[(m0 + g) * OG_PAD + ks + 2*tq];
            uint32_t ah1 = *(const uint32_t*)&Ahi[(m0 + g + 8) * OG_PAD + ks + 2*tq];
            uint32_t ah2 = *(const uint32_t*)&Ahi[(m0 + g) * OG_PAD + ks + 2*tq + 8];
            uint32_t ah3 = *(const uint32_t*)&Ahi[(m0 + g + 8) * OG_PAD + ks + 2*tq + 8];
            uint32_t al0 = *(const uint32_t*)&Alo[(m0 + g) * OG_PAD + ks + 2*tq];
            uint32_t al1 = *(const uint32_t*)&Alo[(m0 + g + 8) * OG_PAD + ks + 2*tq];
            uint32_t al2 = *(const uint32_t*)&Alo[(m0 + g) * OG_PAD + ks + 2*tq + 8];
            uint32_t al3 = *(const uint32_t*)&Alo[(m0 + g + 8) * OG_PAD + ks + 2*tq + 8];
#pragma unroll
            for (int nt = 0; nt < 8; nt++) {
                int brow = nc0 + nt * 8 + g;
                uint32_t bh0 = *(const uint32_t*)&Whi[brow * OG_PAD + ks + 2*tq];
                uint32_t bh1 = *(const uint32_t*)&Whi[brow * OG_PAD + ks + 2*tq + 8];
                uint32_t bl0 = *(const uint32_t*)&Wlo[brow * OG_PAD + ks + 2*tq];
                uint32_t bl1 = *(const uint32_t*)&Wlo[brow * OG_PAD + ks + 2*tq + 8];
                mma_bf16(acc[nt], ah0, ah1, ah2, ah3, bh0, bh1);
                mma_bf16(acc[nt], ah0, ah1, ah2, ah3, bl0, bl1);
                mma_bf16(acc[nt], al0, al1, al2, al3, bh0, bh1);
            }
        }
        if (c < 31) OG_STORE(p ^ 1);
        __syncthreads();
    }
#undef OG_LOAD
#undef OG_STORE

    // epilogue: c0,c1 -> (m0+g, col..col+1); c2,c3 -> (m0+g+8, col..col+1)
#pragma unroll
    for (int nt = 0; nt < 8; nt++) {
        int col = n0 + nc0 + nt * 8 + 2 * tq;
        int r0 = m0 + g, r1 = m0 + g + 8;
        if (col < VOCAB) {
            float bv = ob[col];
            out[(size_t)r0 * VOCAB + col] = acc[nt][0] + bv;
            out[(size_t)r1 * VOCAB + col] = acc[nt][2] + bv;
        }
        if (col + 1 < VOCAB) {
            float bv = ob[col + 1];
            out[(size_t)r0 * VOCAB + col + 1] = acc[nt][1] + bv;
            out[(size_t)r1 * VOCAB + col + 1] = acc[nt][3] + bv;
        }
    }
}

// ---------------- launch ----------------
extern "C" void kernel_launch(void* const* d_in, const int* in_sizes, int n_in,
                              void* d_out, int out_size) {
    const int* seq = (const int*)d_in[0];
    const float* h0 = (const float*)d_in[1];
    const float* c0 = (const float*)d_in[2];
    const float* enc = (const float*)d_in[3];
    const float* embW = (const float*)d_in[4];
    const float* W_ih = (const float*)d_in[5];
    const float* W_hh = (const float*)d_in[6];
    const float* b_ih = (const float*)d_in[7];
    const float* b_hh = (const float*)d_in[8];
    const float* cW = (const float*)d_in[9];
    const float* cb = (const float*)d_in[10];
    const float* oW = (const float*)d_in[11];
    const float* ob = (const float*)d_in[12];

    float* out = (float*)d_out;
    float* out_logits = out;                       // [64, 50257]
    float* out_h = out + (size_t)B * VOCAB;        // [64, 1024]
    float* out_c = out_h + (size_t)B * H;          // [64, 1024]
    float* out_attn = out_c + (size_t)B * H;       // [64, 2048]

    const int ATT_SMEM = (2 * 16 * 1024 + 1024) * 4;   // 135168 B
    const int OG_SMEM = 2 * OG_BUF * 2;                // 61440 B
    cudaFuncSetAttribute(attn_staged_kernel, cudaFuncAttributeMaxDynamicSharedMemorySize, ATT_SMEM);
    cudaFuncSetAttribute(out_gemm_kernel, cudaFuncAttributeMaxDynamicSharedMemorySize, OG_SMEM);

    // 1) A = [emb[seq] || h0]
    prep_kernel<<<64, 256>>>(seq, embW, h0);
    // 2) gates partials: [64,4096] = A @ [W_ih|W_hh]^T, split-K=4
    gemm_kernel<<<dim3(64, 1, 4), 256>>>(0, 2048, 1024, W_ih, W_hh, 0, 4096);
    // 3) LSTM activations -> h, c
    lstm_act_kernel<<<64, 256>>>(c0, b_ih, b_hh, out_h, out_c);
    // 4) attention: smem-staged single pass over encoder_outputs
    attn_staged_kernel<<<dim3(CH, 64), 256, ATT_SMEM>>>(enc);
    attn_combine_kernel<<<64, 256>>>(out_attn);
    // 5) concat GEMM: [64,1024] = A2 @ concat_W^T, split-K=8; finalize -> bf16 hi/lo
    gemm_kernel<<<dim3(16, 1, 8), 256>>>(1, 2048, 2048, cW, nullptr, 1, 1024);
    concat_fin_kernel<<<64, 256>>>(cb);
    // 6) output GEMM via tensor cores (bf16 hi/lo split)
    out_gemm_kernel<<<(VOCAB + 127) / 128, 256, OG_SMEM>>>(oW, ob, out_logits);
}

// round 7
// speedup vs baseline: 1.6155x; 1.0629x over previous
#include <cuda_runtime.h>
#include <cuda_bf16.h>
#include <cstdint>
#include <cstddef>
#include <cmath>

#define DINLINE __device__ __forceinline__

static constexpr int B = 64, H = 1024, E = 1024, S = 2048, VOCAB = 50257;
static constexpr int CH = 16;           // attention S-chunks (128 rows each)

// ---------------- scratch (__device__ globals: allocation-free) ----------------
__device__ unsigned short g_Ah[B * 2048];  // bf16 hi of [emb||h0]
__device__ unsigned short g_Al[B * 2048];  // bf16 lo of [emb||h0]
__device__ float g_gates[4 * B * 4096];    // split-K=4 partials of gates
__device__ float g_h[B * H];               // LSTM output h
__device__ float g_e[B * S];               // raw attention energies
__device__ float g_pm[B * CH];             // per-chunk running max
__device__ float g_pl[B * CH];             // per-chunk running sum
__device__ float g_pctx[B * CH * H];       // per-chunk unnormalized context
__device__ float g_A2[B * 2048];           // [h || context]
__device__ float g_cop[8 * B * H];         // split-K=8 partials of concat GEMM
__device__ unsigned short g_coh[B * H];    // bf16 hi of tanh(concat)
__device__ unsigned short g_col[B * H];    // bf16 lo of tanh(concat)

// ---------------- helpers ----------------
DINLINE void cp16(void* smem_ptr, const void* gptr) {
    uint32_t s = (uint32_t)__cvta_generic_to_shared(smem_ptr);
    asm volatile("cp.async.cg.shared.global [%0], [%1], 16;" :: "r"(s), "l"(gptr) : "memory");
}
DINLINE void cp_commit() { asm volatile("cp.async.commit_group;" ::: "memory"); }
DINLINE void cp_wait1() { asm volatile("cp.async.wait_group 1;" ::: "memory"); }
DINLINE void cp_wait0() { asm volatile("cp.async.wait_group 0;" ::: "memory"); }

DINLINE void mma_bf16(float* c, uint32_t a0, uint32_t a1, uint32_t a2, uint32_t a3,
                      uint32_t b0, uint32_t b1) {
    asm volatile(
        "mma.sync.aligned.m16n8k16.row.col.f32.bf16.bf16.f32 "
        "{%0,%1,%2,%3}, {%4,%5,%6,%7}, {%8,%9}, {%0,%1,%2,%3};"
        : "+f"(c[0]), "+f"(c[1]), "+f"(c[2]), "+f"(c[3])
        : "r"(a0), "r"(a1), "r"(a2), "r"(a3), "r"(b0), "r"(b1));
}

DINLINE uint32_t pack2h(__nv_bfloat16 a, __nv_bfloat16 b) {
    return (uint32_t)__bfloat16_as_ushort(a) | ((uint32_t)__bfloat16_as_ushort(b) << 16);
}

// ---------------- 1) build A = [emb[seq] || h0] as bf16 hi/lo ----------------
__global__ void prep_kernel(const int* __restrict__ seq,
                            const float* __restrict__ embW,
                            const float* __restrict__ h0) {
    int b = blockIdx.x, t = threadIdx.x;
    float4 e4 = ((const float4*)(embW + (size_t)seq[b] * E))[t];
    float4 h4 = ((const float4*)(h0 + (size_t)b * H))[t];
    uint32_t* Ah32 = (uint32_t*)g_Ah;
    uint32_t* Al32 = (uint32_t*)g_Al;
    size_t base = (size_t)b * 1024;   // uint32 index: row of 2048 halves = 1024 u32
    const float* ev = (const float*)&e4;
    const float* hv = (const float*)&h4;
#pragma unroll
    for (int p = 0; p < 2; p++) {
        float v0 = ev[2 * p], v1 = ev[2 * p + 1];
        __nv_bfloat16 h0b = __float2bfloat16_rn(v0), h1b = __float2bfloat16_rn(v1);
        Ah32[base + 2 * t + p] = pack2h(h0b, h1b);
        Al32[base + 2 * t + p] = pack2h(__float2bfloat16_rn(v0 - __bfloat162float(h0b)),
                                        __float2bfloat16_rn(v1 - __bfloat162float(h1b)));
        float w0 = hv[2 * p], w1 = hv[2 * p + 1];
        __nv_bfloat16 g0b = __float2bfloat16_rn(w0), g1b = __float2bfloat16_rn(w1);
        Ah32[base + 512 + 2 * t + p] = pack2h(g0b, g1b);
        Al32[base + 512 + 2 * t + p] = pack2h(__float2bfloat16_rn(w0 - __bfloat162float(g0b)),
                                              __float2bfloat16_rn(w1 - __bfloat162float(g1b)));
    }
}

// ---------------- tensor-core GEMM (bf16 hi/lo 3x): C[64,N] = A[64,K] @ W[N,K]^T ----------------
// aSel: 0 -> g_Ah/g_Al (K=2048), 1 -> g_coh/g_col (K=1024)
// cSel: 0 -> g_gates (+ z*64*N), 1 -> Cout (with bias)
// W(n,k) from W0 if k<Ks else W1 (32-aligned runs never cross Ks).
static constexpr int OG_PAD = 40;       // halves per smem row (conflict-free)
static constexpr int OG_BUF = 15360;    // halves per buffer
__global__ __launch_bounds__(256) void tc_gemm_kernel(
    int aSel, int K, int Ks,
    const float* __restrict__ W0, const float* __restrict__ W1,
    const float* __restrict__ bias, int cSel, float* __restrict__ Cout, int N) {
    extern __shared__ unsigned short smh[];
    const int tid = threadIdx.x, lane = tid & 31, w = tid >> 5;
    const int g = lane >> 2, tq = lane & 3;
    const int n0 = blockIdx.x * 128;

    const int kLen = K / gridDim.z;
    const int kBeg = blockIdx.z * kLen;
    const int nChunk = kLen >> 5;
    const int kstr2 = K >> 1;           // uint32 per A row

    const int wn = tid >> 1;
    const int wkh = (tid & 1) * 16;
    const int gn = n0 + wn;
    const bool wvalid = gn < N;

    const uint32_t* AhU = (const uint32_t*)((aSel == 0) ? g_Ah : g_coh);
    const uint32_t* AlU = (const uint32_t*)((aSel == 0) ? g_Al : g_col);
    float* C = (cSel == 0) ? (g_gates + (size_t)blockIdx.z * 64 * N) : Cout;

    float4 wr[4];
    uint32_t ahr[4], alr[4];

#define OG_LOAD(c) do {                                                       \
        int kc = kBeg + (c) * 32;                                             \
        int kg = kc + wkh;                                                    \
        if (wvalid) {                                                         \
            const float* p_ = (kg < Ks) ? (W0 + (size_t)gn * Ks + kg)         \
                                        : (W1 + (size_t)gn * (K - Ks) + (kg - Ks)); \
            wr[0] = *(const float4*)p_;       wr[1] = *(const float4*)(p_ + 4);  \
            wr[2] = *(const float4*)(p_ + 8); wr[3] = *(const float4*)(p_ + 12); \
        } else {                                                              \
            wr[0] = make_float4(0.f,0.f,0.f,0.f); wr[1]=wr[0]; wr[2]=wr[0]; wr[3]=wr[0]; \
        }                                                                     \
        int kp2 = kc >> 1;                                                    \
        _Pragma("unroll")                                                     \
        for (int j = 0; j < 4; j++) {                                         \
            int flat = tid + j * 256;                                         \
            int am = flat >> 4, ak = flat & 15;                               \
            ahr[j] = AhU[am * kstr2 + kp2 + ak];                              \
            alr[j] = AlU[am * kstr2 + kp2 + ak];                              \
        }                                                                     \
    } while (0)

#define OG_STORE(p) do {                                                      \
        unsigned short* Whi_ = smh + (p) * OG_BUF;                            \
        unsigned short* Wlo_ = Whi_ + 5120;                                   \
        unsigned short* Ahi_ = Whi_ + 10240;                                  \
        unsigned short* Alo_ = Whi_ + 12800;                                  \
        const float* wf = (const float*)wr;                                   \
        _Pragma("unroll")                                                     \
        for (int i = 0; i < 8; i++) {                                         \
            float v0 = wf[2*i], v1 = wf[2*i+1];                               \
            __nv_bfloat16 h0 = __float2bfloat16_rn(v0);                       \
            __nv_bfloat16 h1 = __float2bfloat16_rn(v1);                       \
            __nv_bfloat16 l0 = __float2bfloat16_rn(v0 - __bfloat162float(h0));\
            __nv_bfloat16 l1 = __float2bfloat16_rn(v1 - __bfloat162float(h1));\
            *(uint32_t*)&Whi_[wn * OG_PAD + wkh + 2*i] = pack2h(h0, h1);      \
            *(uint32_t*)&Wlo_[wn * OG_PAD + wkh + 2*i] = pack2h(l0, l1);      \
        }                                                                     \
        _Pragma("unroll")                                                     \
        for (int j = 0; j < 4; j++) {                                         \
            int flat = tid + j * 256;                                         \
            int am = flat >> 4, ak = flat & 15;                               \
            *(uint32_t*)&Ahi_[am * OG_PAD + 2*ak] = ahr[j];                   \
            *(uint32_t*)&Alo_[am * OG_PAD + 2*ak] = alr[j];                   \
        }                                                                     \
    } while (0)

    const int m0 = (w & 3) * 16;
    const int nc0 = (w >> 2) * 64;
    float acc[8][4];
#pragma unroll
    for (int i = 0; i < 8; i++)
#pragma unroll
        for (int j = 0; j < 4; j++) acc[i][j] = 0.f;

    OG_LOAD(0);
    OG_STORE(0);
    __syncthreads();

    for (int c = 0; c < nChunk; c++) {
        int p = c & 1;
        if (c + 1 < nChunk) OG_LOAD(c + 1);
        const unsigned short* Whi = smh + p * OG_BUF;
        const unsigned short* Wlo = Whi + 5120;
        const unsigned short* Ahi = Whi + 10240;
        const unsigned short* Alo = Whi + 12800;
#pragma unroll
        for (int ks = 0; ks < 32; ks += 16) {
            uint32_t ah0 = *(const uint32_t*)&Ahi[(m0 + g) * OG_PAD + ks + 2*tq];
            uint32_t ah1 = *(const uint32_t*)&Ahi[(m0 + g + 8) * OG_PAD + ks + 2*tq];
            uint32_t ah2 = *(const uint32_t*)&Ahi[(m0 + g) * OG_PAD + ks + 2*tq + 8];
            uint32_t ah3 = *(const uint32_t*)&Ahi[(m0 + g + 8) * OG_PAD + ks + 2*tq + 8];
            uint32_t al0 = *(const uint32_t*)&Alo[(m0 + g) * OG_PAD + ks + 2*tq];
            uint32_t al1 = *(const uint32_t*)&Alo[(m0 + g + 8) * OG_PAD + ks + 2*tq];
            uint32_t al2 = *(const uint32_t*)&Alo[(m0 + g) * OG_PAD + ks + 2*tq + 8];
            uint32_t al3 = *(const uint32_t*)&Alo[(m0 + g + 8) * OG_PAD + ks + 2*tq + 8];
#pragma unroll
            for (int nt = 0; nt < 8; nt++) {
                int brow = nc0 + nt * 8 + g;
                uint32_t bh0 = *(const uint32_t*)&Whi[brow * OG_PAD + ks + 2*tq];
                uint32_t bh1 = *(const uint32_t*)&Whi[brow * OG_PAD + ks + 2*tq + 8];
                uint32_t bl0 = *(const uint32_t*)&Wlo[brow * OG_PAD + ks + 2*tq];
                uint32_t bl1 = *(const uint32_t*)&Wlo[brow * OG_PAD + ks + 2*tq + 8];
                mma_bf16(acc[nt], ah0, ah1, ah2, ah3, bh0, bh1);
                mma_bf16(acc[nt], ah0, ah1, ah2, ah3, bl0, bl1);
                mma_bf16(acc[nt], al0, al1, al2, al3, bh0, bh1);
            }
        }
        if (c + 1 < nChunk) OG_STORE(p ^ 1);
        __syncthreads();
    }
#undef OG_LOAD
#undef OG_STORE

#pragma unroll
    for (int nt = 0; nt < 8; nt++) {
        int col = n0 + nc0 + nt * 8 + 2 * tq;
        int r0 = m0 + g, r1 = m0 + g + 8;
        if (col < N) {
            float bv = bias ? bias[col] : 0.f;
            C[(size_t)r0 * N + col] = acc[nt][0] + bv;
            C[(size_t)r1 * N + col] = acc[nt][2] + bv;
        }
        if (col + 1 < N) {
            float bv = bias ? bias[col + 1] : 0.f;
            C[(size_t)r0 * N + col + 1] = acc[nt][1] + bv;
            C[(size_t)r1 * N + col + 1] = acc[nt][3] + bv;
        }
    }
}

// ---------------- 2) LSTM activations (sums 4 split-K partials) ----------------
__global__ void lstm_act_kernel(const float* __restrict__ c0,
                                const float* __restrict__ b_ih,
                                const float* __restrict__ b_hh,
                                float* __restrict__ out_h,
                                float* __restrict__ out_c) {
    int b = blockIdx.x;
#pragma unroll
    for (int r = 0; r < 4; r++) {
        int hid = threadIdx.x + r * 256;
        float gi = b_ih[hid] + b_hh[hid];
        float gf = b_ih[1024 + hid] + b_hh[1024 + hid];
        float gg = b_ih[2048 + hid] + b_hh[2048 + hid];
        float go = b_ih[3072 + hid] + b_hh[3072 + hid];
#pragma unroll
        for (int z = 0; z < 4; z++) {
            const float* gp = g_gates + (size_t)z * 64 * 4096 + (size_t)b * 4096;
            gi += gp[hid];
            gf += gp[1024 + hid];
            gg += gp[2048 + hid];
            go += gp[3072 + hid];
        }
        float cc0 = c0[(size_t)b * H + hid];
        float si = 1.f / (1.f + __expf(-gi));
        float sf = 1.f / (1.f + __expf(-gf));
        float so = 1.f / (1.f + __expf(-go));
        float c = sf * cc0 + si * tanhf(gg);
        float h = so * tanhf(c);
        g_h[(size_t)b * H + hid] = h;
        out_h[(size_t)b * H + hid] = h;
        out_c[(size_t)b * H + hid] = c;
    }
}

// ---------------- 3) smem-staged flash attention (8-row tiles, 3 CTAs/SM) ----------------
__global__ __launch_bounds__(256) void attn_staged_kernel(const float* __restrict__ enc) {
    extern __shared__ float smf[];
    float* buf0 = smf;                 // 8*1024
    float* buf1 = smf + 8 * 1024;      // 8*1024
    float* h_s = smf + 16 * 1024;      // 1024
    __shared__ float e_tile[8];

    int b = blockIdx.y, chunk = blockIdx.x;
    int tid = threadIdx.x, lane = tid & 31, w = tid >> 5;
    int s0 = chunk * (S / CH);
    int cr = w, cc = lane;             // cp.async: row = warp, 8 f4 per lane

    ((float4*)h_s)[tid] = ((const float4*)(g_h + (size_t)b * H))[tid];

#define ISSUE_TILE(t, dst) do {                                                   \
        const float* gsrc = enc + ((size_t)(s0 + (t) * 8 + cr) * 64 + b) * 1024;  \
        _Pragma("unroll")                                                         \
        for (int j = 0; j < 8; j++) {                                             \
            int f4 = cc + j * 32;                                                 \
            cp16((dst) + cr * 1024 + f4 * 4, gsrc + f4 * 4);                      \
        }                                                                         \
        cp_commit();                                                              \
    } while (0)

    ISSUE_TILE(0, buf0);

    float m = -INFINITY, l = 0.f;
    float cx0 = 0.f, cx1 = 0.f, cx2 = 0.f, cx3 = 0.f;

    for (int t = 0; t < 16; t++) {
        float* bufc = (t & 1) ? buf1 : buf0;
        if (t < 15) {
            ISSUE_TILE(t + 1, (t & 1) ? buf0 : buf1);
            cp_wait1();
        } else {
            cp_wait0();
        }
        __syncthreads();

        // dots: warp w computes row w of this 8-row tile (from smem)
        {
            const float* rp = bufc + w * 1024;
            float sum = 0.f;
#pragma unroll
            for (int i = 0; i < 8; i++) {
                float4 ev = *(const float4*)(rp + i * 128 + lane * 4);
                float4 hv = *(const float4*)(h_s + i * 128 + lane * 4);
                sum += ev.x * hv.x + ev.y * hv.y + ev.z * hv.z + ev.w * hv.w;
            }
#pragma unroll
            for (int off = 16; off; off >>= 1) sum += __shfl_xor_sync(0xffffffffu, sum, off);
            if (lane == 0) {
                e_tile[w] = sum;
                g_e[(size_t)b * S + s0 + t * 8 + w] = sum;
            }
        }
        __syncthreads();

        // online softmax + context accumulate (from smem)
        float tm = -INFINITY;
#pragma unroll
        for (int si = 0; si < 8; si++) tm = fmaxf(tm, e_tile[si]);
        float nm = fmaxf(m, tm);
        float sc = __expf(m - nm);     // 0 on first tile
        l *= sc; cx0 *= sc; cx1 *= sc; cx2 *= sc; cx3 *= sc;
#pragma unroll
        for (int si = 0; si < 8; si++) {
            float wt = __expf(e_tile[si] - nm);
            l += wt;
            const float* rp = bufc + si * 1024 + tid;
            cx0 += wt * rp[0];
            cx1 += wt * rp[256];
            cx2 += wt * rp[512];
            cx3 += wt * rp[768];
        }
        m = nm;
        __syncthreads();   // all reads done before next cp.async overwrites
    }
#undef ISSUE_TILE

    int p = b * CH + chunk;
    if (tid == 0) { g_pm[p] = m; g_pl[p] = l; }
    float* pc = g_pctx + (size_t)p * 1024;
    pc[tid] = cx0; pc[tid + 256] = cx1; pc[tid + 512] = cx2; pc[tid + 768] = cx3;
}

// ---------------- 4) combine partials: context, attn output, A2=[h||ctx] ----------------
__global__ void attn_combine_kernel(float* __restrict__ out_attn) {
    int b = blockIdx.x, tid = threadIdx.x;
    float M = -INFINITY;
#pragma unroll
    for (int i = 0; i < CH; i++) M = fmaxf(M, g_pm[b * CH + i]);
    float L = 0.f;
    float em[CH];
#pragma unroll
    for (int i = 0; i < CH; i++) {
        em[i] = __expf(g_pm[b * CH + i] - M);
        L += g_pl[b * CH + i] * em[i];
    }
    float invL = 1.f / L;
#pragma unroll
    for (int r = 0; r < 4; r++) {
        int j = tid + r * 256;
        float v = 0.f;
#pragma unroll
        for (int i = 0; i < CH; i++) v += em[i] * g_pctx[(size_t)(b * CH + i) * 1024 + j];
        v *= invL;
        g_A2[(size_t)b * 2048 + 1024 + j] = v;
        g_A2[(size_t)b * 2048 + j] = g_h[(size_t)b * H + j];
    }
    for (int s = tid; s < S; s += 256)
        out_attn[(size_t)b * S + s] = __expf(g_e[(size_t)b * S + s] - M) * invL;
}

// ---------------- fp32 GEMM for concat: C = A2[64,K] @ W[N,K]^T ----------------
__global__ __launch_bounds__(256) void gemm_kernel(
    int K, const float* __restrict__ W0, int N) {
    __shared__ float As[2][32 * 68];
    __shared__ float Ws[2][32 * 68];
    const float* A = g_A2;
    float* C = g_cop;

    int tid = threadIdx.x;
    int tx = tid & 15, ty = tid >> 4;
    int row = tid >> 2;
    int kk = (tid & 3) << 3;
    int n0 = blockIdx.x * 64;
    int kLen = K / gridDim.z;
    int kBeg = blockIdx.z * kLen;
    C += (size_t)blockIdx.z * 64 * N;
    int ng = n0 + row;
    bool wok = ng < N;

    float4 ar0, ar1, wr0, wr1;
#define LOADT(kc) do {                                                        \
        int kg = (kc) + kk;                                                   \
        const float* ap = A + (size_t)row * K + kg;                           \
        ar0 = *(const float4*)ap; ar1 = *(const float4*)(ap + 4);             \
        if (wok) {                                                            \
            const float* wp = W0 + (size_t)ng * K + kg;                       \
            wr0 = *(const float4*)wp; wr1 = *(const float4*)(wp + 4);         \
        } else { wr0 = make_float4(0.f,0.f,0.f,0.f); wr1 = wr0; }             \
    } while (0)
#define STORET(p) do {                                                        \
        float* as = As[p]; float* ws = Ws[p];                                 \
        as[(kk+0)*68+row]=ar0.x; as[(kk+1)*68+row]=ar0.y;                     \
        as[(kk+2)*68+row]=ar0.z; as[(kk+3)*68+row]=ar0.w;                     \
        as[(kk+4)*68+row]=ar1.x; as[(kk+5)*68+row]=ar1.y;                     \
        as[(kk+6)*68+row]=ar1.z; as[(kk+7)*68+row]=ar1.w;                     \
        ws[(kk+0)*68+row]=wr0.x; ws[(kk+1)*68+row]=wr0.y;                     \
        ws[(kk+2)*68+row]=wr0.z; ws[(kk+3)*68+row]=wr0.w;                     \
        ws[(kk+4)*68+row]=wr1.x; ws[(kk+5)*68+row]=wr1.y;                     \
        ws[(kk+6)*68+row]=wr1.z; ws[(kk+7)*68+row]=wr1.w;                     \
    } while (0)

    float acc[4][4];
#pragma unroll
    for (int i = 0; i < 4; i++)
#pragma unroll
        for (int j = 0; j < 4; j++) acc[i][j] = 0.f;

    LOADT(kBeg);
    STORET(0);
    __syncthreads();

    int nChunk = kLen >> 5;
    for (int c = 0; c < nChunk; c++) {
        int p = c & 1;
        if (c + 1 < nChunk) LOADT(kBeg + (c + 1) * 32);
        const float4* As4 = (const float4*)As[p];
        const float4* Ws4 = (const float4*)Ws[p];
#pragma unroll
        for (int k = 0; k < 32; k++) {
            float4 av = As4[k * 17 + ty];
            float4 bv = Ws4[k * 17 + tx];
#pragma unroll
            for (int i = 0; i < 4; i++) {
                float a = (i == 0) ? av.x : (i == 1) ? av.y : (i == 2) ? av.z : av.w;
                acc[i][0] = fmaf(a, bv.x, acc[i][0]);
                acc[i][1] = fmaf(a, bv.y, acc[i][1]);
                acc[i][2] = fmaf(a, bv.z, acc[i][2]);
                acc[i][3] = fmaf(a, bv.w, acc[i][3]);
            }
        }
        if (c + 1 < nChunk) STORET(p ^ 1);
        __syncthreads();
    }
#undef LOADT
#undef STORET

#pragma unroll
    for (int i = 0; i < 4; i++) {
        int m = ty * 4 + i;
#pragma unroll
        for (int j = 0; j < 4; j++) {
            int n = n0 + tx * 4 + j;
            if (n < N) C[(size_t)m * N + n] = acc[i][j];
        }
    }
}

// ---------------- 5) concat finalize: sum partials + bias + tanh -> bf16 hi/lo ----------------
__global__ void concat_fin_kernel(const float* __restrict__ cb) {
    int b = blockIdx.x, tid = threadIdx.x;
#pragma unroll
    for (int r = 0; r < 4; r++) {
        int j = tid + r * 256;
        float v = cb[j];
#pragma unroll
        for (int z = 0; z < 8; z++)
            v += g_cop[(size_t)z * 64 * 1024 + (size_t)b * 1024 + j];
        v = tanhf(v);
        __nv_bfloat16 hh = __float2bfloat16_rn(v);
        float lo = v - __bfloat162float(hh);
        g_coh[(size_t)b * 1024 + j] = __bfloat16_as_ushort(hh);
        g_col[(size_t)b * 1024 + j] = __bfloat16_as_ushort(__float2bfloat16_rn(lo));
    }
}

// ---------------- launch ----------------
extern "C" void kernel_launch(void* const* d_in, const int* in_sizes, int n_in,
                              void* d_out, int out_size) {
    const int* seq = (const int*)d_in[0];
    const float* h0 = (const float*)d_in[1];
    const float* c0 = (const float*)d_in[2];
    const float* enc = (const float*)d_in[3];
    const float* embW = (const float*)d_in[4];
    const float* W_ih = (const float*)d_in[5];
    const float* W_hh = (const float*)d_in[6];
    const float* b_ih = (const float*)d_in[7];
    const float* b_hh = (const float*)d_in[8];
    const float* cW = (const float*)d_in[9];
    const float* cb = (const float*)d_in[10];
    const float* oW = (const float*)d_in[11];
    const float* ob = (const float*)d_in[12];

    float* out = (float*)d_out;
    float* out_logits = out;                       // [64, 50257]
    float* out_h = out + (size_t)B * VOCAB;        // [64, 1024]
    float* out_c = out_h + (size_t)B * H;          // [64, 1024]
    float* out_attn = out_c + (size_t)B * H;       // [64, 2048]

    const int ATT_SMEM = (16 * 1024 + 1024) * 4;   // 69632 B -> 3 CTAs/SM
    const int OG_SMEM = 2 * OG_BUF * 2;            // 61440 B
    cudaFuncSetAttribute(attn_staged_kernel, cudaFuncAttributeMaxDynamicSharedMemorySize, ATT_SMEM);
    cudaFuncSetAttribute(tc_gemm_kernel, cudaFuncAttributeMaxDynamicSharedMemorySize, OG_SMEM);

    // 1) A = [emb[seq] || h0] -> bf16 hi/lo
    prep_kernel<<<64, 256>>>(seq, embW, h0);
    // 2) gates partials via tensor cores: [64,4096] = A @ [W_ih|W_hh]^T, split-K=4
    tc_gemm_kernel<<<dim3(32, 1, 4), 256, OG_SMEM>>>(0, 2048, 1024, W_ih, W_hh,
                                                     nullptr, 0, nullptr, 4096);
    // 3) LSTM activations -> h, c
    lstm_act_kernel<<<64, 256>>>(c0, b_ih, b_hh, out_h, out_c);
    // 4) attention: smem-staged single pass over encoder_outputs
    attn_staged_kernel<<<dim3(CH, 64), 256, ATT_SMEM>>>(enc);
    attn_combine_kernel<<<64, 256>>>(out_attn);
    // 5) concat GEMM: [64,1024] = A2 @ concat_W^T, split-K=8; finalize -> bf16 hi/lo
    gemm_kernel<<<dim3(16, 1, 8), 256>>>(2048, cW, 1024);
    concat_fin_kernel<<<64, 256>>>(cb);
    // 6) output GEMM via tensor cores (bf16 hi/lo split)
    tc_gemm_kernel<<<dim3((VOCAB + 127) / 128, 1, 1), 256, OG_SMEM>>>(1, 1024, 1024, oW, nullptr,
                                                                      ob, 1, out_logits, VOCAB);
}

// round 8
// speedup vs baseline: 1.7607x; 1.0899x over previous
#include <cuda_runtime.h>
#include <cuda_bf16.h>
#include <cstdint>
#include <cstddef>
#include <cmath>

#define DINLINE __device__ __forceinline__

static constexpr int B = 64, H = 1024, E = 1024, S = 2048, VOCAB = 50257;
static constexpr int CH = 16;           // attention S-chunks (128 rows each)

// ---------------- scratch (__device__ globals: allocation-free) ----------------
__device__ unsigned short g_Ah[B * 2048];  // bf16 hi of [emb||h0]
__device__ unsigned short g_Al[B * 2048];  // bf16 lo of [emb||h0]
__device__ float g_gates[4 * B * 4096];    // split-K=4 partials of gates
__device__ float g_h[B * H];               // LSTM output h
__device__ float g_e[B * S];               // raw attention energies
__device__ float g_pm[B * CH];             // per-chunk running max
__device__ float g_pl[B * CH];             // per-chunk running sum
__device__ float g_pctx[B * CH * H];       // per-chunk unnormalized context
__device__ float g_A2[B * 2048];           // [h || context]
__device__ float g_cop[8 * B * H];         // split-K=8 partials of concat GEMM
__device__ unsigned short g_coh[B * H];    // bf16 hi of tanh(concat)
__device__ unsigned short g_col[B * H];    // bf16 lo of tanh(concat)

// ---------------- helpers ----------------
DINLINE void cp16(void* smem_ptr, const void* gptr) {
    uint32_t s = (uint32_t)__cvta_generic_to_shared(smem_ptr);
    asm volatile("cp.async.cg.shared.global [%0], [%1], 16;" :: "r"(s), "l"(gptr) : "memory");
}
DINLINE void cp_commit() { asm volatile("cp.async.commit_group;" ::: "memory"); }
DINLINE void cp_wait1() { asm volatile("cp.async.wait_group 1;" ::: "memory"); }
DINLINE void cp_wait0() { asm volatile("cp.async.wait_group 0;" ::: "memory"); }

DINLINE void mma_bf16(float* c, uint32_t a0, uint32_t a1, uint32_t a2, uint32_t a3,
                      uint32_t b0, uint32_t b1) {
    asm volatile(
        "mma.sync.aligned.m16n8k16.row.col.f32.bf16.bf16.f32 "
        "{%0,%1,%2,%3}, {%4,%5,%6,%7}, {%8,%9}, {%0,%1,%2,%3};"
        : "+f"(c[0]), "+f"(c[1]), "+f"(c[2]), "+f"(c[3])
        : "r"(a0), "r"(a1), "r"(a2), "r"(a3), "r"(b0), "r"(b1));
}

DINLINE uint32_t pack2h(__nv_bfloat16 a, __nv_bfloat16 b) {
    return (uint32_t)__bfloat16_as_ushort(a) | ((uint32_t)__bfloat16_as_ushort(b) << 16);
}
// packed 2x f32 -> bf16x2: returns {lo16=bf16(lo), hi16=bf16(hi)}
DINLINE uint32_t cvt2bf(float lo, float hi) {
    uint32_t r;
    asm("cvt.rn.bf16x2.f32 %0, %1, %2;" : "=r"(r) : "f"(hi), "f"(lo));
    return r;
}

// ---------------- 1) build A = [emb[seq] || h0] as bf16 hi/lo ----------------
__global__ void prep_kernel(const int* __restrict__ seq,
                            const float* __restrict__ embW,
                            const float* __restrict__ h0) {
    int b = blockIdx.x, t = threadIdx.x;
    float4 e4 = ((const float4*)(embW + (size_t)seq[b] * E))[t];
    float4 h4 = ((const float4*)(h0 + (size_t)b * H))[t];
    uint32_t* Ah32 = (uint32_t*)g_Ah;
    uint32_t* Al32 = (uint32_t*)g_Al;
    size_t base = (size_t)b * 1024;
    const float* ev = (const float*)&e4;
    const float* hv = (const float*)&h4;
#pragma unroll
    for (int p = 0; p < 2; p++) {
        float v0 = ev[2 * p], v1 = ev[2 * p + 1];
        uint32_t hp = cvt2bf(v0, v1);
        float f0 = __uint_as_float(hp << 16);
        float f1 = __uint_as_float(hp & 0xFFFF0000u);
        Ah32[base + 2 * t + p] = hp;
        Al32[base + 2 * t + p] = cvt2bf(v0 - f0, v1 - f1);
        float w0 = hv[2 * p], w1 = hv[2 * p + 1];
        uint32_t gp = cvt2bf(w0, w1);
        float g0 = __uint_as_float(gp << 16);
        float g1 = __uint_as_float(gp & 0xFFFF0000u);
        Ah32[base + 512 + 2 * t + p] = gp;
        Al32[base + 512 + 2 * t + p] = cvt2bf(w0 - g0, w1 - g1);
    }
}

// ---------------- tensor-core GEMM (bf16 hi/lo 3x): C[64,N] = A[64,K] @ W[N,K]^T ----------------
// aSel: 0 -> g_Ah/g_Al, 1 -> g_coh/g_col.  cSel: 0 -> g_gates (+z*64*N), 1 -> Cout (+bias)
// A tiles arrive via cp.async; W fp32 -> regs -> packed bf16 hi/lo -> smem.
static constexpr int OG_PAD = 40;       // halves per smem row
static constexpr int OG_BUF = 15360;    // halves per buffer
// buffer layout (halves): Whi[128*40]=0, Wlo=5120, Ahi[64*40]=10240, Alo=12800
__global__ __launch_bounds__(256, 2) void tc_gemm_kernel(
    int aSel, int K, int Ks,
    const float* __restrict__ W0, const float* __restrict__ W1,
    const float* __restrict__ bias, int cSel, float* __restrict__ Cout, int N) {
    extern __shared__ unsigned short smh[];
    const int tid = threadIdx.x, lane = tid & 31, w = tid >> 5;
    const int g = lane >> 2, tq = lane & 3;
    const int n0 = blockIdx.x * 128;

    const int kLen = K / gridDim.z;
    const int kBeg = blockIdx.z * kLen;
    const int nChunk = kLen >> 5;
    const int kstr2 = K >> 1;           // uint32 per A row

    const int wn = tid >> 1;
    const int wkh = (tid & 1) * 16;
    const int gn = n0 + wn;
    const bool wvalid = gn < N;

    const uint32_t* AhU = (const uint32_t*)((aSel == 0) ? g_Ah : g_coh);
    const uint32_t* AlU = (const uint32_t*)((aSel == 0) ? g_Al : g_col);
    float* C = (cSel == 0) ? (g_gates + (size_t)blockIdx.z * 64 * N) : Cout;

    // A cp.async mapping: 2 slots/thread, 512 slots = 64 rows x (4 hi + 4 lo) 16B chunks
    const int s0i = tid, s1i = tid + 256;

    float4 wr[4];

#define OGA_ISSUE(c, p) do {                                                  \
        int kp2 = (kBeg + (c) * 32) >> 1;                                     \
        unsigned short* Ahi_ = smh + (p) * OG_BUF + 10240;                    \
        unsigned short* Alo_ = smh + (p) * OG_BUF + 12800;                    \
        _Pragma("unroll")                                                     \
        for (int j = 0; j < 2; j++) {                                         \
            int s = (j == 0) ? s0i : s1i;                                     \
            int am = s >> 3, q = s & 7;                                       \
            int ak = (q & 3) * 4;                                             \
            const uint32_t* src = ((q < 4) ? AhU : AlU) + (size_t)am * kstr2 + kp2 + ak; \
            unsigned short* dst = ((q < 4) ? Ahi_ : Alo_) + am * OG_PAD + 2 * ak; \
            cp16(dst, src);                                                   \
        }                                                                     \
        cp_commit();                                                          \
    } while (0)

#define OGW_LOAD(c) do {                                                      \
        int kg = kBeg + (c) * 32 + wkh;                                       \
        if (wvalid) {                                                         \
            const float* p_ = (kg < Ks) ? (W0 + (size_t)gn * Ks + kg)         \
                                        : (W1 + (size_t)gn * (K - Ks) + (kg - Ks)); \
            wr[0] = *(const float4*)p_;       wr[1] = *(const float4*)(p_ + 4);  \
            wr[2] = *(const float4*)(p_ + 8); wr[3] = *(const float4*)(p_ + 12); \
        } else {                                                              \
            wr[0] = make_float4(0.f,0.f,0.f,0.f); wr[1]=wr[0]; wr[2]=wr[0]; wr[3]=wr[0]; \
        }                                                                     \
    } while (0)

#define OGW_STORE(p) do {                                                     \
        unsigned short* Whi_ = smh + (p) * OG_BUF;                            \
        unsigned short* Wlo_ = Whi_ + 5120;                                   \
        const float* wf = (const float*)wr;                                   \
        _Pragma("unroll")                                                     \
        for (int i = 0; i < 8; i++) {                                         \
            float v0 = wf[2*i], v1 = wf[2*i+1];                               \
            uint32_t hp = cvt2bf(v0, v1);                                     \
            float f0 = __uint_as_float(hp << 16);                             \
            float f1 = __uint_as_float(hp & 0xFFFF0000u);                     \
            uint32_t lp = cvt2bf(v0 - f0, v1 - f1);                           \
            *(uint32_t*)&Whi_[wn * OG_PAD + wkh + 2*i] = hp;                  \
            *(uint32_t*)&Wlo_[wn * OG_PAD + wkh + 2*i] = lp;                  \
        }                                                                     \
    } while (0)

    const int m0 = (w & 3) * 16;
    const int nc0 = (w >> 2) * 64;
    float acc[8][4];
#pragma unroll
    for (int i = 0; i < 8; i++)
#pragma unroll
        for (int j = 0; j < 4; j++) acc[i][j] = 0.f;

    OGA_ISSUE(0, 0);
    OGW_LOAD(0);
    OGW_STORE(0);
    cp_wait0();
    __syncthreads();

    for (int c = 0; c < nChunk; c++) {
        int p = c & 1;
        if (c + 1 < nChunk) {
            OGA_ISSUE(c + 1, p ^ 1);
            OGW_LOAD(c + 1);
        }
        const unsigned short* Whi = smh + p * OG_BUF;
        const unsigned short* Wlo = Whi + 5120;
        const unsigned short* Ahi = Whi + 10240;
        const unsigned short* Alo = Whi + 12800;
#pragma unroll
        for (int ks = 0; ks < 32; ks += 16) {
            uint32_t ah0 = *(const uint32_t*)&Ahi[(m0 + g) * OG_PAD + ks + 2*tq];
            uint32_t ah1 = *(const uint32_t*)&Ahi[(m0 + g + 8) * OG_PAD + ks + 2*tq];
            uint32_t ah2 = *(const uint32_t*)&Ahi[(m0 + g) * OG_PAD + ks + 2*tq + 8];
            uint32_t ah3 = *(const uint32_t*)&Ahi[(m0 + g + 8) * OG_PAD + ks + 2*tq + 8];
            uint32_t al0 = *(const uint32_t*)&Alo[(m0 + g) * OG_PAD + ks + 2*tq];
            uint32_t al1 = *(const uint32_t*)&Alo[(m0 + g + 8) * OG_PAD + ks + 2*tq];
            uint32_t al2 = *(const uint32_t*)&Alo[(m0 + g) * OG_PAD + ks + 2*tq + 8];
            uint32_t al3 = *(const uint32_t*)&Alo[(m0 + g + 8) * OG_PAD + ks + 2*tq + 8];
#pragma unroll
            for (int nt = 0; nt < 8; nt++) {
                int brow = nc0 + nt * 8 + g;
                uint32_t bh0 = *(const uint32_t*)&Whi[brow * OG_PAD + ks + 2*tq];
                uint32_t bh1 = *(const uint32_t*)&Whi[brow * OG_PAD + ks + 2*tq + 8];
                uint32_t bl0 = *(const uint32_t*)&Wlo[brow * OG_PAD + ks + 2*tq];
                uint32_t bl1 = *(const uint32_t*)&Wlo[brow * OG_PAD + ks + 2*tq + 8];
                mma_bf16(acc[nt], ah0, ah1, ah2, ah3, bh0, bh1);
                mma_bf16(acc[nt], ah0, ah1, ah2, ah3, bl0, bl1);
                mma_bf16(acc[nt], al0, al1, al2, al3, bh0, bh1);
            }
        }
        if (c + 1 < nChunk) {
            OGW_STORE(p ^ 1);
            cp_wait0();
        }
        __syncthreads();
    }
#undef OGA_ISSUE
#undef OGW_LOAD
#undef OGW_STORE

#pragma unroll
    for (int nt = 0; nt < 8; nt++) {
        int col = n0 + nc0 + nt * 8 + 2 * tq;
        int r0 = m0 + g, r1 = m0 + g + 8;
        if (col < N) {
            float bv = bias ? bias[col] : 0.f;
            C[(size_t)r0 * N + col] = acc[nt][0] + bv;
            C[(size_t)r1 * N + col] = acc[nt][2] + bv;
        }
        if (col + 1 < N) {
            float bv = bias ? bias[col + 1] : 0.f;
            C[(size_t)r0 * N + col + 1] = acc[nt][1] + bv;
            C[(size_t)r1 * N + col + 1] = acc[nt][3] + bv;
        }
    }
}

// ---------------- 2) LSTM activations (sums 4 split-K partials) ----------------
__global__ void lstm_act_kernel(const float* __restrict__ c0,
                                const float* __restrict__ b_ih,
                                const float* __restrict__ b_hh,
                                float* __restrict__ out_h,
                                float* __restrict__ out_c) {
    int b = blockIdx.x;
#pragma unroll
    for (int r = 0; r < 4; r++) {
        int hid = threadIdx.x + r * 256;
        float gi = b_ih[hid] + b_hh[hid];
        float gf = b_ih[1024 + hid] + b_hh[1024 + hid];
        float gg = b_ih[2048 + hid] + b_hh[2048 + hid];
        float go = b_ih[3072 + hid] + b_hh[3072 + hid];
#pragma unroll
        for (int z = 0; z < 4; z++) {
            const float* gp = g_gates + (size_t)z * 64 * 4096 + (size_t)b * 4096;
            gi += gp[hid];
            gf += gp[1024 + hid];
            gg += gp[2048 + hid];
            go += gp[3072 + hid];
        }
        float cc0 = c0[(size_t)b * H + hid];
        float si = 1.f / (1.f + __expf(-gi));
        float sf = 1.f / (1.f + __expf(-gf));
        float so = 1.f / (1.f + __expf(-go));
        float c = sf * cc0 + si * tanhf(gg);
        float h = so * tanhf(c);
        g_h[(size_t)b * H + hid] = h;
        out_h[(size_t)b * H + hid] = h;
        out_c[(size_t)b * H + hid] = c;
    }
}

// ---------------- 3) barrier-free warp-private flash attention ----------------
// grid (CH, B), 256 threads. Warp w owns row w of each 8-row tile end-to-end:
// cp.async its row, per-warp wait, dot, warp-private online softmax with
// register context (32 floats/lane). No block barriers in mainloop.
__global__ __launch_bounds__(256) void attn_staged_kernel(const float* __restrict__ enc) {
    extern __shared__ float smf[];
    float* buf0 = smf;                 // 8*1024
    float* buf1 = smf + 8 * 1024;      // 8*1024
    float* h_s = smf + 16 * 1024;      // 1024
    __shared__ float m_sh[8], l_sh[8];

    int b = blockIdx.y, chunk = blockIdx.x;
    int tid = threadIdx.x, lane = tid & 31, w = tid >> 5;
    int s0 = chunk * (S / CH);

    ((float4*)h_s)[tid] = ((const float4*)(g_h + (size_t)b * H))[tid];

#define ISSUE_ROW(t, dst) do {                                                    \
        const float* gsrc = enc + ((size_t)(s0 + (t) * 8 + w) * 64 + b) * 1024;   \
        _Pragma("unroll")                                                         \
        for (int j = 0; j < 8; j++) {                                             \
            int f4 = lane + j * 32;                                               \
            cp16((dst) + w * 1024 + f4 * 4, gsrc + f4 * 4);                       \
        }                                                                         \
        cp_commit();                                                              \
    } while (0)

    ISSUE_ROW(0, buf0);
    __syncthreads();     // h_s visible to all warps; no further block barriers in loop

    float m = -INFINITY, l = 0.f;
    float ctx[8][4];
#pragma unroll
    for (int i = 0; i < 8; i++)
#pragma unroll
        for (int j = 0; j < 4; j++) ctx[i][j] = 0.f;

    for (int t = 0; t < 16; t++) {
        float* bufc = (t & 1) ? buf1 : buf0;
        if (t < 15) {
            ISSUE_ROW(t + 1, (t & 1) ? buf0 : buf1);
            cp_wait1();
        } else {
            cp_wait0();
        }
        const float* rp = bufc + w * 1024;
        float4 ev[8];
        float sum = 0.f;
#pragma unroll
        for (int i = 0; i < 8; i++) {
            ev[i] = *(const float4*)(rp + i * 128 + lane * 4);
            float4 hv = *(const float4*)(h_s + i * 128 + lane * 4);
            sum += ev[i].x * hv.x + ev[i].y * hv.y + ev[i].z * hv.z + ev[i].w * hv.w;
        }
#pragma unroll
        for (int off = 16; off; off >>= 1) sum += __shfl_xor_sync(0xffffffffu, sum, off);
        if (lane == 0) g_e[(size_t)b * S + s0 + t * 8 + w] = sum;

        float nm = fmaxf(m, sum);
        float sc = __expf(m - nm);     // 0 on first row
        float wt = __expf(sum - nm);
        l = l * sc + wt;
#pragma unroll
        for (int i = 0; i < 8; i++) {
            ctx[i][0] = ctx[i][0] * sc + wt * ev[i].x;
            ctx[i][1] = ctx[i][1] * sc + wt * ev[i].y;
            ctx[i][2] = ctx[i][2] * sc + wt * ev[i].z;
            ctx[i][3] = ctx[i][3] * sc + wt * ev[i].w;
        }
        m = nm;
    }
#undef ISSUE_ROW

    // merge 8 warp-partials: warp w parks its ctx in buf0 row w
    float* park = buf0 + w * 1024;
#pragma unroll
    for (int i = 0; i < 8; i++)
        *(float4*)(park + i * 128 + lane * 4) = make_float4(ctx[i][0], ctx[i][1], ctx[i][2], ctx[i][3]);
    if (lane == 0) { m_sh[w] = m; l_sh[w] = l; }
    __syncthreads();

    float M = -INFINITY;
#pragma unroll
    for (int i = 0; i < 8; i++) M = fmaxf(M, m_sh[i]);
    float ew[8];
    float L = 0.f;
#pragma unroll
    for (int i = 0; i < 8; i++) {
        ew[i] = __expf(m_sh[i] - M);
        L += l_sh[i] * ew[i];
    }
    int p = b * CH + chunk;
    if (tid == 0) { g_pm[p] = M; g_pl[p] = L; }
    float* pc = g_pctx + (size_t)p * 1024;
#pragma unroll
    for (int r = 0; r < 4; r++) {
        int col = tid + r * 256;
        float v = 0.f;
#pragma unroll
        for (int i = 0; i < 8; i++) v += ew[i] * buf0[i * 1024 + col];
        pc[col] = v;
    }
}

// ---------------- 4) combine partials: context, attn output, A2=[h||ctx] ----------------
__global__ void attn_combine_kernel(float* __restrict__ out_attn) {
    int b = blockIdx.x, tid = threadIdx.x;
    float M = -INFINITY;
#pragma unroll
    for (int i = 0; i < CH; i++) M = fmaxf(M, g_pm[b * CH + i]);
    float L = 0.f;
    float em[CH];
#pragma unroll
    for (int i = 0; i < CH; i++) {
        em[i] = __expf(g_pm[b * CH + i] - M);
        L += g_pl[b * CH + i] * em[i];
    }
    float invL = 1.f / L;
#pragma unroll
    for (int r = 0; r < 4; r++) {
        int j = tid + r * 256;
        float v = 0.f;
#pragma unroll
        for (int i = 0; i < CH; i++) v += em[i] * g_pctx[(size_t)(b * CH + i) * 1024 + j];
        v *= invL;
        g_A2[(size_t)b * 2048 + 1024 + j] = v;
        g_A2[(size_t)b * 2048 + j] = g_h[(size_t)b * H + j];
    }
    for (int s = tid; s < S; s += 256)
        out_attn[(size_t)b * S + s] = __expf(g_e[(size_t)b * S + s] - M) * invL;
}

// ---------------- fp32 GEMM for concat: C = A2[64,K] @ W[N,K]^T ----------------
__global__ __launch_bounds__(256) void gemm_kernel(
    int K, const float* __restrict__ W0, int N) {
    __shared__ float As[2][32 * 68];
    __shared__ float Ws[2][32 * 68];
    const float* A = g_A2;
    float* C = g_cop;

    int tid = threadIdx.x;
    int tx = tid & 15, ty = tid >> 4;
    int row = tid >> 2;
    int kk = (tid & 3) << 3;
    int n0 = blockIdx.x * 64;
    int kLen = K / gridDim.z;
    int kBeg = blockIdx.z * kLen;
    C += (size_t)blockIdx.z * 64 * N;
    int ng = n0 + row;
    bool wok = ng < N;

    float4 ar0, ar1, wr0, wr1;
#define LOADT(kc) do {                                                        \
        int kg = (kc) + kk;                                                   \
        const float* ap = A + (size_t)row * K + kg;                           \
        ar0 = *(const float4*)ap; ar1 = *(const float4*)(ap + 4);             \
        if (wok) {                                                            \
            const float* wp = W0 + (size_t)ng * K + kg;                       \
            wr0 = *(const float4*)wp; wr1 = *(const float4*)(wp + 4);         \
        } else { wr0 = make_float4(0.f,0.f,0.f,0.f); wr1 = wr0; }             \
    } while (0)
#define STORET(p) do {                                                        \
        float* as = As[p]; float* ws = Ws[p];                                 \
        as[(kk+0)*68+row]=ar0.x; as[(kk+1)*68+row]=ar0.y;                     \
        as[(kk+2)*68+row]=ar0.z; as[(kk+3)*68+row]=ar0.w;                     \
        as[(kk+4)*68+row]=ar1.x; as[(kk+5)*68+row]=ar1.y;                     \
        as[(kk+6)*68+row]=ar1.z; as[(kk+7)*68+row]=ar1.w;                     \
        ws[(kk+0)*68+row]=wr0.x; ws[(kk+1)*68+row]=wr0.y;                     \
        ws[(kk+2)*68+row]=wr0.z; ws[(kk+3)*68+row]=wr0.w;                     \
        ws[(kk+4)*68+row]=wr1.x; ws[(kk+5)*68+row]=wr1.y;                     \
        ws[(kk+6)*68+row]=wr1.z; ws[(kk+7)*68+row]=wr1.w;                     \
    } while (0)

    float acc[4][4];
#pragma unroll
    for (int i = 0; i < 4; i++)
#pragma unroll
        for (int j = 0; j < 4; j++) acc[i][j] = 0.f;

    LOADT(kBeg);
    STORET(0);
    __syncthreads();

    int nChunk = kLen >> 5;
    for (int c = 0; c < nChunk; c++) {
        int p = c & 1;
        if (c + 1 < nChunk) LOADT(kBeg + (c + 1) * 32);
        const float4* As4 = (const float4*)As[p];
        const float4* Ws4 = (const float4*)Ws[p];
#pragma unroll
        for (int k = 0; k < 32; k++) {
            float4 av = As4[k * 17 + ty];
            float4 bv = Ws4[k * 17 + tx];
#pragma unroll
            for (int i = 0; i < 4; i++) {
                float a = (i == 0) ? av.x : (i == 1) ? av.y : (i == 2) ? av.z : av.w;
                acc[i][0] = fmaf(a, bv.x, acc[i][0]);
                acc[i][1] = fmaf(a, bv.y, acc[i][1]);
                acc[i][2] = fmaf(a, bv.z, acc[i][2]);
                acc[i][3] = fmaf(a, bv.w, acc[i][3]);
            }
        }
        if (c + 1 < nChunk) STORET(p ^ 1);
        __syncthreads();
    }
#undef LOADT
#undef STORET

#pragma unroll
    for (int i = 0; i < 4; i++) {
        int m = ty * 4 + i;
#pragma unroll
        for (int j = 0; j < 4; j++) {
            int n = n0 + tx * 4 + j;
            if (n < N) C[(size_t)m * N + n] = acc[i][j];
        }
    }
}

// ---------------- 5) concat finalize: sum partials + bias + tanh -> bf16 hi/lo ----------------
__global__ void concat_fin_kernel(const float* __restrict__ cb) {
    int b = blockIdx.x, tid = threadIdx.x;
#pragma unroll
    for (int r = 0; r < 4; r++) {
        int j = tid + r * 256;
        float v = cb[j];
#pragma unroll
        for (int z = 0; z < 8; z++)
            v += g_cop[(size_t)z * 64 * 1024 + (size_t)b * 1024 + j];
        v = tanhf(v);
        __nv_bfloat16 hh = __float2bfloat16_rn(v);
        float lo = v - __bfloat162float(hh);
        g_coh[(size_t)b * 1024 + j] = __bfloat16_as_ushort(hh);
        g_col[(size_t)b * 1024 + j] = __bfloat16_as_ushort(__float2bfloat16_rn(lo));
    }
}

// ---------------- launch ----------------
extern "C" void kernel_launch(void* const* d_in, const int* in_sizes, int n_in,
                              void* d_out, int out_size) {
    const int* seq = (const int*)d_in[0];
    const float* h0 = (const float*)d_in[1];
    const float* c0 = (const float*)d_in[2];
    const float* enc = (const float*)d_in[3];
    const float* embW = (const float*)d_in[4];
    const float* W_ih = (const float*)d_in[5];
    const float* W_hh = (const float*)d_in[6];
    const float* b_ih = (const float*)d_in[7];
    const float* b_hh = (const float*)d_in[8];
    const float* cW = (const float*)d_in[9];
    const float* cb = (const float*)d_in[10];
    const float* oW = (const float*)d_in[11];
    const float* ob = (const float*)d_in[12];

    float* out = (float*)d_out;
    float* out_logits = out;                       // [64, 50257]
    float* out_h = out + (size_t)B * VOCAB;        // [64, 1024]
    float* out_c = out_h + (size_t)B * H;          // [64, 1024]
    float* out_attn = out_c + (size_t)B * H;       // [64, 2048]

    const int ATT_SMEM = (16 * 1024 + 1024) * 4;   // 69632 B -> 3 CTAs/SM
    const int OG_SMEM = 2 * OG_BUF * 2;            // 61440 B -> 2 CTAs/SM
    cudaFuncSetAttribute(attn_staged_kernel, cudaFuncAttributeMaxDynamicSharedMemorySize, ATT_SMEM);
    cudaFuncSetAttribute(tc_gemm_kernel, cudaFuncAttributeMaxDynamicSharedMemorySize, OG_SMEM);

    // 1) A = [emb[seq] || h0] -> bf16 hi/lo
    prep_kernel<<<64, 256>>>(seq, embW, h0);
    // 2) gates partials via tensor cores: [64,4096] = A @ [W_ih|W_hh]^T, split-K=4
    tc_gemm_kernel<<<dim3(32, 1, 4), 256, OG_SMEM>>>(0, 2048, 1024, W_ih, W_hh,
                                                     nullptr, 0, nullptr, 4096);
    // 3) LSTM activations -> h, c
    lstm_act_kernel<<<64, 256>>>(c0, b_ih, b_hh, out_h, out_c);
    // 4) attention: barrier-free warp-private single pass over encoder_outputs
    attn_staged_kernel<<<dim3(CH, 64), 256, ATT_SMEM>>>(enc);
    attn_combine_kernel<<<64, 256>>>(out_attn);
    // 5) concat GEMM: [64,1024] = A2 @ concat_W^T, split-K=8; finalize -> bf16 hi/lo
    gemm_kernel<<<dim3(16, 1, 8), 256>>>(2048, cW, 1024);
    concat_fin_kernel<<<64, 256>>>(cb);
    // 6) output GEMM via tensor cores (bf16 hi/lo split)
    tc_gemm_kernel<<<dim3((VOCAB + 127) / 128, 1, 1), 256, OG_SMEM>>>(1, 1024, 1024, oW, nullptr,
                                                                      ob, 1, out_logits, VOCAB);
}